// round 2
// baseline (speedup 1.0000x reference)
#include <cuda_runtime.h>
#include <cstdint>

#define NQ 65536
#define NC 2048

typedef unsigned long long ull;

// ------- device scratch (static __device__ globals: allocation-free) -------
__device__ float g_X[NQ * 128];    // [query_codes 64 | xyz_emb 63 | 0]
__device__ float g_DIR[NQ * 32];   // [dir_emb 27 | 0 x5]
__device__ float g_H1[NQ * 128];
__device__ float g_H2[NQ * 128];
__device__ float g_D[NQ * 64];
__device__ float g_W0p[128 * 128];
__device__ float g_W2p[256 * 128];
__device__ float g_Wdp[160 * 64];

// ------------------------- f32x2 helpers -----------------------------------
__device__ __forceinline__ ull pk2(float lo, float hi) {
    ull r; asm("mov.b64 %0,{%1,%2};" : "=l"(r) : "f"(lo), "f"(hi)); return r;
}
__device__ __forceinline__ void fma2(ull& c, ull a, ull b) {
    asm("fma.rn.f32x2 %0,%1,%2,%0;" : "+l"(c) : "l"(a), "l"(b));
}
__device__ __forceinline__ float2 up2(ull v) {
    float2 r; asm("mov.b64 {%0,%1},%2;" : "=f"(r.x), "=f"(r.y) : "l"(v)); return r;
}

// ------------------------- weight prep -------------------------------------
__global__ void prep_weights(const float* __restrict__ W0,
                             const float* __restrict__ W2,
                             const float* __restrict__ Wd) {
    const int T0 = 128 * 128, T2 = 256 * 128, TD = 160 * 64;
    int total = T0 + T2 + TD;
    for (int i = blockIdx.x * blockDim.x + threadIdx.x; i < total;
         i += gridDim.x * blockDim.x) {
        if (i < T0) {
            int r = i >> 7, c = i & 127;
            g_W0p[i] = (r < 127) ? W0[r * 128 + c] : 0.f;
        } else if (i < T0 + T2) {
            int j = i - T0; int r = j >> 7, c = j & 127;
            float v = 0.f;
            if (r < 127)       v = W2[r * 128 + c];        // input_xyz rows
            else if (r >= 128) v = W2[(r - 1) * 128 + c];  // h rows
            g_W2p[j] = v;
        } else {
            int j = i - T0 - T2; int r = j >> 6, c = j & 63;
            g_Wdp[j] = (r < 155) ? Wd[r * 64 + c] : 0.f;
        }
    }
}

// --------------------- pack xyz / dir embeddings ---------------------------
__global__ void pack_inputs(const float* __restrict__ xyzdir) {
    const int TA = NQ * 64;
    const int total = NQ * 64 + NQ * 32;
    for (int i = blockIdx.x * blockDim.x + threadIdx.x; i < total;
         i += gridDim.x * blockDim.x) {
        if (i < TA) {
            int q = i >> 6, e = i & 63;
            g_X[q * 128 + 64 + e] = (e < 63) ? xyzdir[q * 90 + e] : 0.f;
        } else {
            int j = i - TA; int q = j >> 5, e = j & 31;
            g_DIR[j] = (e < 27) ? xyzdir[q * 90 + 63 + e] : 0.f;
        }
    }
}

// --------------- KNN(16) + weighted code interpolation ---------------------
__global__ void __launch_bounds__(128) knn_interp(const int* __restrict__ indices,
                                                  const float* __restrict__ qp,
                                                  const float* __restrict__ cpos,
                                                  const float* __restrict__ codes) {
    __shared__ float scp[NC * 3];
    __shared__ float s_w[128 * 16];
    __shared__ int   s_i[128 * 16];
    int tid = threadIdx.x;
    int ib = indices[0];
    const float* cp = cpos + (size_t)ib * NC * 3;
    const float* cc = codes + (size_t)ib * NC * 64;
    for (int i = tid; i < NC * 3; i += 128) scp[i] = cp[i];
    __syncthreads();

    int q = blockIdx.x * 128 + tid;
    float qx = qp[q * 3 + 0], qy = qp[q * 3 + 1], qz = qp[q * 3 + 2];

    // sorted-ascending packed keys: bits[31:11]=truncated d2 bits, [10:0]=idx
    unsigned bk[16];
#pragma unroll
    for (int j = 0; j < 16; j++) bk[j] = 0xFFFFFFFFu;

    for (int c = 0; c < NC; c++) {
        float dx = qx - scp[c * 3 + 0];
        float dy = qy - scp[c * 3 + 1];
        float dz = qz - scp[c * 3 + 2];
        float d2 = fmaf(dx, dx, fmaf(dy, dy, dz * dz));
        unsigned key = (__float_as_uint(d2) & 0xFFFFF800u) | (unsigned)c;
        if (key < bk[15]) {
            unsigned cur = key;
#pragma unroll
            for (int j = 0; j < 16; j++) {
                unsigned lo = (bk[j] < cur) ? bk[j] : cur;
                unsigned hi = (bk[j] < cur) ? cur : bk[j];
                bk[j] = lo; cur = hi;
            }
        }
    }

    // exact distances -> normalized 1/d2 weights (DIST_SCALE=2)
    float w[16]; int ci[16]; float wsum = 0.f;
#pragma unroll
    for (int k = 0; k < 16; k++) {
        int c = (int)(bk[k] & 0x7FFu); ci[k] = c;
        float dx = qx - scp[c * 3 + 0];
        float dy = qy - scp[c * 3 + 1];
        float dz = qz - scp[c * 3 + 2];
        float d2 = fmaf(dx, dx, fmaf(dy, dy, dz * dz)) + 1e-16f;
        w[k] = 1.0f / d2; wsum += w[k];
    }
    float inv = 1.0f / wsum;
#pragma unroll
    for (int k = 0; k < 16; k++) {
        s_w[tid * 16 + k] = w[k] * inv;
        s_i[tid * 16 + k] = ci[k];
    }
    __syncwarp();

    // warp-cooperative gather: lanes cover 64 code dims, coalesced rows
    int lane = tid & 31;
    int wbase = tid & ~31;
    for (int s = 0; s < 32; s++) {
        int t = wbase + s;
        float a0 = 0.f, a1 = 0.f;
#pragma unroll
        for (int k = 0; k < 16; k++) {
            int cix = s_i[t * 16 + k];
            float wk = s_w[t * 16 + k];
            const float* row = cc + cix * 64;
            a0 = fmaf(wk, row[lane], a0);
            a1 = fmaf(wk, row[lane + 32], a1);
        }
        int qq = blockIdx.x * 128 + t;
        g_X[qq * 128 + lane] = a0;
        g_X[qq * 128 + 32 + lane] = a1;
    }
}

// ------------- tiled GEMM body: C = act([A1|A2] @ W + b) -------------------
// 128-row block, NO cols, K = NT*32 (first NT1 tiles from A1). f32x2 FFMA.
template <int NT, int NT1, int NO, bool RELU>
__device__ __forceinline__ void gemm_body(const float* __restrict__ A1, int lda1,
                                          const float* __restrict__ A2, int lda2,
                                          const float* __restrict__ W,
                                          const float* __restrict__ bias,
                                          float* __restrict__ C) {
    constexpr int TN = NO / 16;
    __shared__ float As[32][132];
    __shared__ float Ws[32][NO];

    int tid = threadIdx.x;
    int tx = tid & 15, ty = tid >> 4;
    int rowBlk = blockIdx.x * 128;

    ull acc[4][TN];
#pragma unroll
    for (int i = 0; i < 4; i++)
#pragma unroll
        for (int j = 0; j < TN; j++) acc[i][j] = 0ULL;

#pragma unroll
    for (int t = 0; t < NT; ++t) {
        const float* src; int ld;
        if (t < NT1) { src = A1 + (size_t)rowBlk * lda1 + t * 32;         ld = lda1; }
        else         { src = A2 + (size_t)rowBlk * lda2 + (t - NT1) * 32; ld = lda2; }
#pragma unroll
        for (int it = 0; it < 4; ++it) {
            int r = (tid >> 3) + it * 32;
            int c4 = (tid & 7) * 4;
            float4 v = *reinterpret_cast<const float4*>(src + (size_t)r * ld + c4);
            As[c4 + 0][r] = v.x; As[c4 + 1][r] = v.y;
            As[c4 + 2][r] = v.z; As[c4 + 3][r] = v.w;
        }
        constexpr int WIT = (32 * NO / 4) / 256;
#pragma unroll
        for (int it = 0; it < WIT; ++it) {
            int idx = tid + it * 256;
            int k = idx / (NO / 4);
            int j4 = idx % (NO / 4);
            float4 v = *reinterpret_cast<const float4*>(W + (size_t)(t * 32 + k) * NO + j4 * 4);
            *reinterpret_cast<float4*>(&Ws[k][j4 * 4]) = v;
        }
        __syncthreads();
#pragma unroll
        for (int k = 0; k < 32; k++) {
            float av[8];
#pragma unroll
            for (int i = 0; i < 8; i += 4) {
                float4 v = *reinterpret_cast<const float4*>(&As[k][ty * 8 + i]);
                av[i] = v.x; av[i + 1] = v.y; av[i + 2] = v.z; av[i + 3] = v.w;
            }
            ull ap[4];
#pragma unroll
            for (int i = 0; i < 4; i++) ap[i] = pk2(av[2 * i], av[2 * i + 1]);
            float wvs[TN];
#pragma unroll
            for (int c = 0; c < TN; c += 4) {
                float4 wv = *reinterpret_cast<const float4*>(&Ws[k][tx * TN + c]);
                wvs[c] = wv.x; wvs[c + 1] = wv.y; wvs[c + 2] = wv.z; wvs[c + 3] = wv.w;
            }
#pragma unroll
            for (int c = 0; c < TN; c++) {
                ull wd = pk2(wvs[c], wvs[c]);
#pragma unroll
                for (int i = 0; i < 4; i++) fma2(acc[i][c], ap[i], wd);
            }
        }
        __syncthreads();
    }

    float bv[TN];
#pragma unroll
    for (int c = 0; c < TN; c++) bv[c] = bias[tx * TN + c];
#pragma unroll
    for (int rp = 0; rp < 4; rp++) {
        float2 vals[TN];
#pragma unroll
        for (int c = 0; c < TN; c++) {
            float2 v = up2(acc[rp][c]);
            v.x += bv[c]; v.y += bv[c];
            if (RELU) { v.x = fmaxf(v.x, 0.f); v.y = fmaxf(v.y, 0.f); }
            vals[c] = v;
        }
        int row0 = rowBlk + ty * 8 + rp * 2;
        float* out0 = C + (size_t)row0 * NO + tx * TN;
        float* out1 = out0 + NO;
#pragma unroll
        for (int c4 = 0; c4 < TN; c4 += 4) {
            *reinterpret_cast<float4*>(out0 + c4) =
                make_float4(vals[c4].x, vals[c4 + 1].x, vals[c4 + 2].x, vals[c4 + 3].x);
            *reinterpret_cast<float4*>(out1 + c4) =
                make_float4(vals[c4].y, vals[c4 + 1].y, vals[c4 + 2].y, vals[c4 + 3].y);
        }
    }
}

// --------- GEMM wrappers (globals referenced directly in device code) ------
__global__ void __launch_bounds__(256) gemm0(const float* b0) {
    gemm_body<4, 4, 128, true>(g_X, 128, nullptr, 0, g_W0p, b0, g_H1);
}
__global__ void __launch_bounds__(256) gemm1(const float* W1, const float* b1) {
    gemm_body<4, 4, 128, true>(g_H1, 128, nullptr, 0, W1, b1, g_H2);
}
__global__ void __launch_bounds__(256) gemm2(const float* b2) {
    gemm_body<8, 4, 128, true>(g_X, 128, g_H2, 128, g_W2p, b2, g_H1);
}
__global__ void __launch_bounds__(256) gemm3(const float* W3, const float* b3) {
    gemm_body<4, 4, 128, true>(g_H1, 128, nullptr, 0, W3, b3, g_H2);
}
__global__ void __launch_bounds__(256) gemmf(const float* Wf, const float* bf) {
    gemm_body<4, 4, 128, false>(g_H2, 128, nullptr, 0, Wf, bf, g_H1);
}
__global__ void __launch_bounds__(256) gemmd(const float* bd) {
    gemm_body<5, 4, 64, true>(g_H1, 128, g_DIR, 32, g_Wdp, bd, g_D);
}

// ---------------- tail: sigma = h@Ws+bs, rgb = d@Wr+br ---------------------
__global__ void __launch_bounds__(256) tail_kernel(const float* __restrict__ Wsig,
                                                   const float* __restrict__ bs,
                                                   const float* __restrict__ Wr,
                                                   const float* __restrict__ br,
                                                   float* __restrict__ out) {
    __shared__ float sWs[128];
    __shared__ float sWr[192];
    int tid = threadIdx.x;
    if (tid < 128) sWs[tid] = Wsig[tid];
    if (tid < 192) sWr[tid] = Wr[tid];
    __syncthreads();

    int q = blockIdx.x * 256 + tid;
    const float* h = g_H2 + (size_t)q * 128;
    float sig = 0.f;
#pragma unroll
    for (int k = 0; k < 128; k += 4) {
        float4 hv = *reinterpret_cast<const float4*>(h + k);
        sig = fmaf(hv.x, sWs[k + 0], sig);
        sig = fmaf(hv.y, sWs[k + 1], sig);
        sig = fmaf(hv.z, sWs[k + 2], sig);
        sig = fmaf(hv.w, sWs[k + 3], sig);
    }
    sig += bs[0];

    const float* d = g_D + (size_t)q * 64;
    float r0 = br[0], r1 = br[1], r2 = br[2];
#pragma unroll
    for (int k = 0; k < 64; k++) {
        float dv = d[k];
        r0 = fmaf(dv, sWr[k * 3 + 0], r0);
        r1 = fmaf(dv, sWr[k * 3 + 1], r1);
        r2 = fmaf(dv, sWr[k * 3 + 2], r2);
    }
    *reinterpret_cast<float4*>(out + (size_t)q * 4) = make_float4(r0, r1, r2, sig);
}

// ---------------------------------------------------------------------------
extern "C" void kernel_launch(void* const* d_in, const int* in_sizes, int n_in,
                              void* d_out, int out_size) {
    const int*   indices = (const int*)  d_in[0];
    const float* qp      = (const float*)d_in[1];
    const float* xyzdir  = (const float*)d_in[2];
    const float* cpos    = (const float*)d_in[3];
    const float* codes   = (const float*)d_in[4];
    const float* W0 = (const float*)d_in[5],  *b0 = (const float*)d_in[6];
    const float* W1 = (const float*)d_in[7],  *b1 = (const float*)d_in[8];
    const float* W2 = (const float*)d_in[9],  *b2 = (const float*)d_in[10];
    const float* W3 = (const float*)d_in[11], *b3 = (const float*)d_in[12];
    const float* Wf = (const float*)d_in[13], *bf = (const float*)d_in[14];
    const float* Wd = (const float*)d_in[15], *bd = (const float*)d_in[16];
    const float* Ws = (const float*)d_in[17], *bs = (const float*)d_in[18];
    const float* Wr = (const float*)d_in[19], *br = (const float*)d_in[20];
    float* out = (float*)d_out;

    prep_weights<<<232, 256>>>(W0, W2, Wd);
    pack_inputs<<<1024, 256>>>(xyzdir);
    knn_interp<<<NQ / 128, 128>>>(indices, qp, cpos, codes);
    gemm0<<<NQ / 128, 256>>>(b0);
    gemm1<<<NQ / 128, 256>>>(W1, b1);
    gemm2<<<NQ / 128, 256>>>(b2);
    gemm3<<<NQ / 128, 256>>>(W3, b3);
    gemmf<<<NQ / 128, 256>>>(Wf, bf);
    gemmd<<<NQ / 128, 256>>>(bd);
    tail_kernel<<<NQ / 256, 256>>>(Ws, bs, Wr, br, out);
}

// round 3
// speedup vs baseline: 1.1681x; 1.1681x over previous
#include <cuda_runtime.h>
#include <cstdint>

#define NQ 65536
#define NC 2048

typedef unsigned long long ull;

// ------- device scratch (static __device__ globals: allocation-free) -------
__device__ float g_X[NQ * 128];    // [query_codes 64 | xyz_emb 63 | 0]
__device__ float g_DIR[NQ * 32];   // [dir_emb 27 | 0 x5]
__device__ float g_H1[NQ * 128];
__device__ float g_H2[NQ * 128];
__device__ float g_D[NQ * 64];
__device__ float g_W0p[128 * 128];
__device__ float g_W2p[256 * 128];
__device__ float g_Wdp[160 * 64];

// ------------------------- f32x2 helpers -----------------------------------
__device__ __forceinline__ ull pk2(float lo, float hi) {
    ull r; asm("mov.b64 %0,{%1,%2};" : "=l"(r) : "f"(lo), "f"(hi)); return r;
}
__device__ __forceinline__ void fma2(ull& c, ull a, ull b) {
    asm("fma.rn.f32x2 %0,%1,%2,%0;" : "+l"(c) : "l"(a), "l"(b));
}
__device__ __forceinline__ float2 up2(ull v) {
    float2 r; asm("mov.b64 {%0,%1},%2;" : "=f"(r.x), "=f"(r.y) : "l"(v)); return r;
}

// ------------------------- weight prep -------------------------------------
__global__ void prep_weights(const float* __restrict__ W0,
                             const float* __restrict__ W2,
                             const float* __restrict__ Wd) {
    const int T0 = 128 * 128, T2 = 256 * 128, TD = 160 * 64;
    int total = T0 + T2 + TD;
    for (int i = blockIdx.x * blockDim.x + threadIdx.x; i < total;
         i += gridDim.x * blockDim.x) {
        if (i < T0) {
            int r = i >> 7, c = i & 127;
            g_W0p[i] = (r < 127) ? W0[r * 128 + c] : 0.f;
        } else if (i < T0 + T2) {
            int j = i - T0; int r = j >> 7, c = j & 127;
            float v = 0.f;
            if (r < 127)       v = W2[r * 128 + c];        // input_xyz rows
            else if (r >= 128) v = W2[(r - 1) * 128 + c];  // h rows
            g_W2p[j] = v;
        } else {
            int j = i - T0 - T2; int r = j >> 6, c = j & 63;
            g_Wdp[j] = (r < 155) ? Wd[r * 64 + c] : 0.f;
        }
    }
}

// --------------------- pack xyz / dir embeddings ---------------------------
__global__ void pack_inputs(const float* __restrict__ xyzdir) {
    const int TA = NQ * 64;
    const int total = NQ * 64 + NQ * 32;
    for (int i = blockIdx.x * blockDim.x + threadIdx.x; i < total;
         i += gridDim.x * blockDim.x) {
        if (i < TA) {
            int q = i >> 6, e = i & 63;
            g_X[q * 128 + 64 + e] = (e < 63) ? xyzdir[q * 90 + e] : 0.f;
        } else {
            int j = i - TA; int q = j >> 5, e = j & 31;
            g_DIR[j] = (e < 27) ? xyzdir[q * 90 + 63 + e] : 0.f;
        }
    }
}

// --------------- KNN(16) + weighted code interpolation ---------------------
__global__ void __launch_bounds__(128) knn_interp(const int* __restrict__ indices,
                                                  const float* __restrict__ qp,
                                                  const float* __restrict__ cpos,
                                                  const float* __restrict__ codes) {
    __shared__ float scx[NC], scy[NC], scz[NC];   // SoA positions
    __shared__ float s_w[128 * 16];
    __shared__ int   s_i[128 * 16];
    int tid = threadIdx.x;
    int ib = indices[0];
    const float* cp = cpos + (size_t)ib * NC * 3;
    const float* cc = codes + (size_t)ib * NC * 64;
    for (int c = tid; c < NC; c += 128) {
        scx[c] = cp[c * 3 + 0];
        scy[c] = cp[c * 3 + 1];
        scz[c] = cp[c * 3 + 2];
    }
    __syncthreads();

    int q = blockIdx.x * 128 + tid;
    float qx = qp[q * 3 + 0], qy = qp[q * 3 + 1], qz = qp[q * 3 + 2];

    // sorted-ascending packed keys: bits[31:11]=truncated d2 bits, [10:0]=idx
    unsigned bk[16];
#pragma unroll
    for (int j = 0; j < 16; j++) bk[j] = 0xFFFFFFFFu;

    for (int c = 0; c < NC; c += 4) {
        float4 sx = *reinterpret_cast<const float4*>(&scx[c]);
        float4 sy = *reinterpret_cast<const float4*>(&scy[c]);
        float4 sz = *reinterpret_cast<const float4*>(&scz[c]);
#pragma unroll
        for (int i = 0; i < 4; i++) {
            float dx = qx - ((const float*)&sx)[i];
            float dy = qy - ((const float*)&sy)[i];
            float dz = qz - ((const float*)&sz)[i];
            float d2 = fmaf(dx, dx, fmaf(dy, dy, dz * dz));
            unsigned key = (__float_as_uint(d2) & 0xFFFFF800u) | (unsigned)(c + i);
            if (key < bk[15]) {
                unsigned cur = key;
#pragma unroll
                for (int j = 0; j < 16; j++) {
                    unsigned mn = min(bk[j], cur);
                    unsigned mx = max(bk[j], cur);
                    bk[j] = mn; cur = mx;
                }
            }
        }
    }

    // exact distances -> normalized 1/d2 weights (DIST_SCALE=2)
    float w[16]; int ci[16]; float wsum = 0.f;
#pragma unroll
    for (int k = 0; k < 16; k++) {
        int c = (int)(bk[k] & 0x7FFu); ci[k] = c;
        float dx = qx - scx[c];
        float dy = qy - scy[c];
        float dz = qz - scz[c];
        float d2 = fmaf(dx, dx, fmaf(dy, dy, dz * dz)) + 1e-16f;
        w[k] = 1.0f / d2; wsum += w[k];
    }
    float inv = 1.0f / wsum;
#pragma unroll
    for (int k = 0; k < 16; k++) {
        s_w[tid * 16 + k] = w[k] * inv;
        s_i[tid * 16 + k] = ci[k];
    }
    __syncwarp();

    // warp-cooperative gather: lanes cover 64 code dims, coalesced rows
    int lane = tid & 31;
    int wbase = tid & ~31;
    for (int s = 0; s < 32; s++) {
        int t = wbase + s;
        float a0 = 0.f, a1 = 0.f;
#pragma unroll
        for (int k = 0; k < 16; k++) {
            int cix = s_i[t * 16 + k];
            float wk = s_w[t * 16 + k];
            const float* row = cc + cix * 64;
            a0 = fmaf(wk, row[lane], a0);
            a1 = fmaf(wk, row[lane + 32], a1);
        }
        int qq = blockIdx.x * 128 + t;
        g_X[qq * 128 + lane] = a0;
        g_X[qq * 128 + 32 + lane] = a1;
    }
}

// ------------- tiled GEMM body: C = act([A1|A2] @ W + b) -------------------
// 128-row block, NO cols, K = NT*32 (first NT1 tiles from A1). f32x2 FFMA.
template <int NT, int NT1, int NO, bool RELU>
__device__ __forceinline__ void gemm_body(const float* __restrict__ A1, int lda1,
                                          const float* __restrict__ A2, int lda2,
                                          const float* __restrict__ W,
                                          const float* __restrict__ bias,
                                          float* __restrict__ C) {
    constexpr int TN = NO / 16;
    __shared__ float As[32][132];
    __shared__ float Ws[32][NO];

    int tid = threadIdx.x;
    int tx = tid & 15, ty = tid >> 4;
    int rowBlk = blockIdx.x * 128;

    ull acc[4][TN];
#pragma unroll
    for (int i = 0; i < 4; i++)
#pragma unroll
        for (int j = 0; j < TN; j++) acc[i][j] = 0ULL;

#pragma unroll
    for (int t = 0; t < NT; ++t) {
        const float* src; int ld;
        if (t < NT1) { src = A1 + (size_t)rowBlk * lda1 + t * 32;         ld = lda1; }
        else         { src = A2 + (size_t)rowBlk * lda2 + (t - NT1) * 32; ld = lda2; }
#pragma unroll
        for (int it = 0; it < 4; ++it) {
            int r = (tid >> 3) + it * 32;
            int c4 = (tid & 7) * 4;
            float4 v = *reinterpret_cast<const float4*>(src + (size_t)r * ld + c4);
            As[c4 + 0][r] = v.x; As[c4 + 1][r] = v.y;
            As[c4 + 2][r] = v.z; As[c4 + 3][r] = v.w;
        }
        constexpr int WIT = (32 * NO / 4) / 256;
#pragma unroll
        for (int it = 0; it < WIT; ++it) {
            int idx = tid + it * 256;
            int k = idx / (NO / 4);
            int j4 = idx % (NO / 4);
            float4 v = *reinterpret_cast<const float4*>(W + (size_t)(t * 32 + k) * NO + j4 * 4);
            *reinterpret_cast<float4*>(&Ws[k][j4 * 4]) = v;
        }
        __syncthreads();
#pragma unroll
        for (int k = 0; k < 32; k++) {
            ull ap[4];
            {
                float4 va = *reinterpret_cast<const float4*>(&As[k][ty * 8]);
                ap[0] = pk2(va.x, va.y); ap[1] = pk2(va.z, va.w);
                float4 vb = *reinterpret_cast<const float4*>(&As[k][ty * 8 + 4]);
                ap[2] = pk2(vb.x, vb.y); ap[3] = pk2(vb.z, vb.w);
            }
#pragma unroll
            for (int c4 = 0; c4 < TN; c4 += 4) {
                float4 wv = *reinterpret_cast<const float4*>(&Ws[k][tx * TN + c4]);
                {
                    ull wd = pk2(wv.x, wv.x);
#pragma unroll
                    for (int i = 0; i < 4; i++) fma2(acc[i][c4 + 0], ap[i], wd);
                }
                {
                    ull wd = pk2(wv.y, wv.y);
#pragma unroll
                    for (int i = 0; i < 4; i++) fma2(acc[i][c4 + 1], ap[i], wd);
                }
                {
                    ull wd = pk2(wv.z, wv.z);
#pragma unroll
                    for (int i = 0; i < 4; i++) fma2(acc[i][c4 + 2], ap[i], wd);
                }
                {
                    ull wd = pk2(wv.w, wv.w);
#pragma unroll
                    for (int i = 0; i < 4; i++) fma2(acc[i][c4 + 3], ap[i], wd);
                }
            }
        }
        __syncthreads();
    }

    float bv[TN];
#pragma unroll
    for (int c = 0; c < TN; c++) bv[c] = bias[tx * TN + c];
#pragma unroll
    for (int rp = 0; rp < 4; rp++) {
        float2 vals[TN];
#pragma unroll
        for (int c = 0; c < TN; c++) {
            float2 v = up2(acc[rp][c]);
            v.x += bv[c]; v.y += bv[c];
            if (RELU) { v.x = fmaxf(v.x, 0.f); v.y = fmaxf(v.y, 0.f); }
            vals[c] = v;
        }
        int row0 = rowBlk + ty * 8 + rp * 2;
        float* out0 = C + (size_t)row0 * NO + tx * TN;
        float* out1 = out0 + NO;
#pragma unroll
        for (int c4 = 0; c4 < TN; c4 += 4) {
            *reinterpret_cast<float4*>(out0 + c4) =
                make_float4(vals[c4].x, vals[c4 + 1].x, vals[c4 + 2].x, vals[c4 + 3].x);
            *reinterpret_cast<float4*>(out1 + c4) =
                make_float4(vals[c4].y, vals[c4 + 1].y, vals[c4 + 2].y, vals[c4 + 3].y);
        }
    }
}

// --------- GEMM wrappers (force 2 CTAs/SM via reg cap) ---------------------
__global__ void __launch_bounds__(256, 2) gemm0(const float* b0) {
    gemm_body<4, 4, 128, true>(g_X, 128, nullptr, 0, g_W0p, b0, g_H1);
}
__global__ void __launch_bounds__(256, 2) gemm1(const float* W1, const float* b1) {
    gemm_body<4, 4, 128, true>(g_H1, 128, nullptr, 0, W1, b1, g_H2);
}
__global__ void __launch_bounds__(256, 2) gemm2(const float* b2) {
    gemm_body<8, 4, 128, true>(g_X, 128, g_H2, 128, g_W2p, b2, g_H1);
}
__global__ void __launch_bounds__(256, 2) gemm3(const float* W3, const float* b3) {
    gemm_body<4, 4, 128, true>(g_H1, 128, nullptr, 0, W3, b3, g_H2);
}
__global__ void __launch_bounds__(256, 2) gemmf(const float* Wf, const float* bf) {
    gemm_body<4, 4, 128, false>(g_H2, 128, nullptr, 0, Wf, bf, g_H1);
}
__global__ void __launch_bounds__(256, 2) gemmd(const float* bd) {
    gemm_body<5, 4, 64, true>(g_H1, 128, g_DIR, 32, g_Wdp, bd, g_D);
}

// ---------------- tail: sigma = h@Ws+bs, rgb = d@Wr+br ---------------------
__global__ void __launch_bounds__(256) tail_kernel(const float* __restrict__ Wsig,
                                                   const float* __restrict__ bs,
                                                   const float* __restrict__ Wr,
                                                   const float* __restrict__ br,
                                                   float* __restrict__ out) {
    __shared__ float sWs[128];
    __shared__ float sWr[192];
    int tid = threadIdx.x;
    if (tid < 128) sWs[tid] = Wsig[tid];
    if (tid < 192) sWr[tid] = Wr[tid];
    __syncthreads();

    int q = blockIdx.x * 256 + tid;
    const float* h = g_H2 + (size_t)q * 128;
    float sig = 0.f;
#pragma unroll
    for (int k = 0; k < 128; k += 4) {
        float4 hv = *reinterpret_cast<const float4*>(h + k);
        sig = fmaf(hv.x, sWs[k + 0], sig);
        sig = fmaf(hv.y, sWs[k + 1], sig);
        sig = fmaf(hv.z, sWs[k + 2], sig);
        sig = fmaf(hv.w, sWs[k + 3], sig);
    }
    sig += bs[0];

    const float* d = g_D + (size_t)q * 64;
    float r0 = br[0], r1 = br[1], r2 = br[2];
#pragma unroll
    for (int k = 0; k < 64; k++) {
        float dv = d[k];
        r0 = fmaf(dv, sWr[k * 3 + 0], r0);
        r1 = fmaf(dv, sWr[k * 3 + 1], r1);
        r2 = fmaf(dv, sWr[k * 3 + 2], r2);
    }
    *reinterpret_cast<float4*>(out + (size_t)q * 4) = make_float4(r0, r1, r2, sig);
}

// ---------------------------------------------------------------------------
extern "C" void kernel_launch(void* const* d_in, const int* in_sizes, int n_in,
                              void* d_out, int out_size) {
    const int*   indices = (const int*)  d_in[0];
    const float* qp      = (const float*)d_in[1];
    const float* xyzdir  = (const float*)d_in[2];
    const float* cpos    = (const float*)d_in[3];
    const float* codes   = (const float*)d_in[4];
    const float* W0 = (const float*)d_in[5],  *b0 = (const float*)d_in[6];
    const float* W1 = (const float*)d_in[7],  *b1 = (const float*)d_in[8];
    const float* W2 = (const float*)d_in[9],  *b2 = (const float*)d_in[10];
    const float* W3 = (const float*)d_in[11], *b3 = (const float*)d_in[12];
    const float* Wf = (const float*)d_in[13], *bf = (const float*)d_in[14];
    const float* Wd = (const float*)d_in[15], *bd = (const float*)d_in[16];
    const float* Ws = (const float*)d_in[17], *bs = (const float*)d_in[18];
    const float* Wr = (const float*)d_in[19], *br = (const float*)d_in[20];
    float* out = (float*)d_out;

    prep_weights<<<232, 256>>>(W0, W2, Wd);
    pack_inputs<<<1024, 256>>>(xyzdir);
    knn_interp<<<NQ / 128, 128>>>(indices, qp, cpos, codes);
    gemm0<<<NQ / 128, 256>>>(b0);
    gemm1<<<NQ / 128, 256>>>(W1, b1);
    gemm2<<<NQ / 128, 256>>>(b2);
    gemm3<<<NQ / 128, 256>>>(W3, b3);
    gemmf<<<NQ / 128, 256>>>(Wf, bf);
    gemmd<<<NQ / 128, 256>>>(bd);
    tail_kernel<<<NQ / 256, 256>>>(Ws, bs, Wr, br, out);
}

// round 5
// speedup vs baseline: 1.2771x; 1.0933x over previous
#include <cuda_runtime.h>
#include <cstdint>

#define NQ 65536
#define NC 2048
#define AS 132   // activation smem row stride (floats)
#define WS 144   // weight-tile smem row stride (floats)

typedef unsigned long long ull;

// ------- device scratch (static __device__ globals: allocation-free) -------
__device__ float g_X[NQ * 128];    // [query_codes 64 | xyz_emb 63 | 0]
__device__ float g_DIR[NQ * 32];   // [dir_emb 27 | 0 x5]
__device__ float g_U[NQ * 128];    // X @ W2x   (skip-path partial)
__device__ float g_V[NQ * 64];     // dir @ Wd_dir + bd
__device__ float g_W0p[128 * 128];
__device__ float g_W2xp[128 * 128];
__device__ float g_W2hp[128 * 128];
__device__ float g_Wdfp[128 * 64];

// ------------------------- f32x2 helpers -----------------------------------
__device__ __forceinline__ ull pk2(float lo, float hi) {
    ull r; asm("mov.b64 %0,{%1,%2};" : "=l"(r) : "f"(lo), "f"(hi)); return r;
}
__device__ __forceinline__ void fma2(ull& c, ull a, ull b) {
    asm("fma.rn.f32x2 %0,%1,%2,%0;" : "+l"(c) : "l"(a), "l"(b));
}
__device__ __forceinline__ float2 up2(ull v) {
    float2 r; asm("mov.b64 {%0,%1},%2;" : "=f"(r.x), "=f"(r.y) : "l"(v)); return r;
}
// weight-column swizzle: group g at base g*8 + (g>>2)*4  (injective, gaps>=8,
// 16B-aligned, phase lanes hit 8 distinct bank quads -> conflict-free LDS.128)
__device__ __forceinline__ int wsw(int col) {
    int g = col >> 3;
    return g * 8 + (g >> 2) * 4 + (col & 7);
}

// ------------------------- weight prep -------------------------------------
__global__ void prep_weights(const float* __restrict__ W0,
                             const float* __restrict__ W2,
                             const float* __restrict__ Wd) {
    const int T0 = 16384, T1 = 16384, T2 = 16384, T3 = 8192;
    int total = T0 + T1 + T2 + T3;
    for (int i = blockIdx.x * blockDim.x + threadIdx.x; i < total;
         i += gridDim.x * blockDim.x) {
        if (i < T0) {
            int r = i >> 7, c = i & 127;
            g_W0p[i] = (r < 127) ? W0[r * 128 + c] : 0.f;
        } else if (i < T0 + T1) {
            int j = i - T0; int r = j >> 7, c = j & 127;
            g_W2xp[j] = (r < 127) ? W2[r * 128 + c] : 0.f;
        } else if (i < T0 + T1 + T2) {
            int j = i - T0 - T1; int r = j >> 7, c = j & 127;
            g_W2hp[j] = W2[(127 + r) * 128 + c];
        } else {
            int j = i - T0 - T1 - T2;
            g_Wdfp[j] = Wd[j];          // rows 0..127 of Wd
        }
    }
}

// --------------------- pack xyz / dir embeddings ---------------------------
__global__ void pack_inputs(const float* __restrict__ xyzdir) {
    const int TA = NQ * 64;
    const int total = NQ * 64 + NQ * 32;
    for (int i = blockIdx.x * blockDim.x + threadIdx.x; i < total;
         i += gridDim.x * blockDim.x) {
        if (i < TA) {
            int q = i >> 6, e = i & 63;
            g_X[q * 128 + 64 + e] = (e < 63) ? xyzdir[q * 90 + e] : 0.f;
        } else {
            int j = i - TA; int q = j >> 5, e = j & 31;
            g_DIR[j] = (e < 27) ? xyzdir[q * 90 + 63 + e] : 0.f;
        }
    }
}

// ---------------- V = dir @ Wd[128:155] + bd  ------------------------------
__global__ void __launch_bounds__(256) vcomp(const float* __restrict__ Wd,
                                             const float* __restrict__ bd) {
    __shared__ float sw[27 * 64];
    __shared__ float sb[64];
    int tid = threadIdx.x;
    for (int i = tid; i < 27 * 64; i += 256) sw[i] = Wd[128 * 64 + i];
    if (tid < 64) sb[tid] = bd[tid];
    __syncthreads();
    int idx = blockIdx.x * 256 + tid;        // NQ*16 threads
    int q = idx >> 4, c0 = (idx & 15) * 4;
    float a0 = sb[c0], a1 = sb[c0 + 1], a2 = sb[c0 + 2], a3 = sb[c0 + 3];
#pragma unroll
    for (int k = 0; k < 27; k++) {
        float dv = g_DIR[q * 32 + k];
        a0 = fmaf(dv, sw[k * 64 + c0 + 0], a0);
        a1 = fmaf(dv, sw[k * 64 + c0 + 1], a1);
        a2 = fmaf(dv, sw[k * 64 + c0 + 2], a2);
        a3 = fmaf(dv, sw[k * 64 + c0 + 3], a3);
    }
    *reinterpret_cast<float4*>(g_V + (size_t)q * 64 + c0) = make_float4(a0, a1, a2, a3);
}

// --------------- KNN(16) + weighted code interpolation ---------------------
__global__ void __launch_bounds__(128) knn_interp(const int* __restrict__ indices,
                                                  const float* __restrict__ qp,
                                                  const float* __restrict__ cpos,
                                                  const float* __restrict__ codes) {
    __shared__ float scx[NC], scy[NC], scz[NC];
    __shared__ float s_w[128 * 16];
    __shared__ int   s_i[128 * 16];
    int tid = threadIdx.x;
    int ib = indices[0];
    const float* cp = cpos + (size_t)ib * NC * 3;
    const float* cc = codes + (size_t)ib * NC * 64;
    for (int c = tid; c < NC; c += 128) {
        scx[c] = cp[c * 3 + 0];
        scy[c] = cp[c * 3 + 1];
        scz[c] = cp[c * 3 + 2];
    }
    __syncthreads();

    int q = blockIdx.x * 128 + tid;
    float qx = qp[q * 3 + 0], qy = qp[q * 3 + 1], qz = qp[q * 3 + 2];

    unsigned bk[16];
#pragma unroll
    for (int j = 0; j < 16; j++) bk[j] = 0xFFFFFFFFu;

    for (int c = 0; c < NC; c += 4) {
        float4 sx = *reinterpret_cast<const float4*>(&scx[c]);
        float4 sy = *reinterpret_cast<const float4*>(&scy[c]);
        float4 sz = *reinterpret_cast<const float4*>(&scz[c]);
#pragma unroll
        for (int i = 0; i < 4; i++) {
            float dx = qx - ((const float*)&sx)[i];
            float dy = qy - ((const float*)&sy)[i];
            float dz = qz - ((const float*)&sz)[i];
            float d2 = fmaf(dx, dx, fmaf(dy, dy, dz * dz));
            unsigned key = (__float_as_uint(d2) & 0xFFFFF800u) | (unsigned)(c + i);
            if (key < bk[15]) {
                unsigned cur = key;
#pragma unroll
                for (int j = 0; j < 16; j++) {
                    unsigned mn = min(bk[j], cur);
                    unsigned mx = max(bk[j], cur);
                    bk[j] = mn; cur = mx;
                }
            }
        }
    }

    float w[16]; int ci[16]; float wsum = 0.f;
#pragma unroll
    for (int k = 0; k < 16; k++) {
        int c = (int)(bk[k] & 0x7FFu); ci[k] = c;
        float dx = qx - scx[c];
        float dy = qy - scy[c];
        float dz = qz - scz[c];
        float d2 = fmaf(dx, dx, fmaf(dy, dy, dz * dz)) + 1e-16f;
        w[k] = 1.0f / d2; wsum += w[k];
    }
    float inv = 1.0f / wsum;
#pragma unroll
    for (int k = 0; k < 16; k++) {
        s_w[tid * 16 + k] = w[k] * inv;
        s_i[tid * 16 + k] = ci[k];
    }
    __syncwarp();

    int lane = tid & 31;
    int wbase2 = tid & ~31;
    for (int s = 0; s < 32; s++) {
        int t = wbase2 + s;
        float a0 = 0.f, a1 = 0.f;
#pragma unroll
        for (int k = 0; k < 16; k++) {
            int cix = s_i[t * 16 + k];
            float wk = s_w[t * 16 + k];
            const float* row = cc + cix * 64;
            a0 = fmaf(wk, row[lane], a0);
            a1 = fmaf(wk, row[lane + 32], a1);
        }
        int qq = blockIdx.x * 128 + t;
        g_X[qq * 128 + lane] = a0;
        g_X[qq * 128 + 32 + lane] = a1;
    }
}

// ===================== fused MLP (entire network) ==========================
#define SMEM_FLOATS (128 * AS + 2 * 32 * WS + 128 + 192)

__global__ void __launch_bounds__(256, 2) fused_mlp(
    const float* __restrict__ W1, const float* __restrict__ W3,
    const float* __restrict__ Wf,
    const float* __restrict__ b0, const float* __restrict__ b1,
    const float* __restrict__ b2, const float* __restrict__ b3,
    const float* __restrict__ bf,
    const float* __restrict__ Wsig, const float* __restrict__ bs,
    const float* __restrict__ Wr,   const float* __restrict__ br,
    float* __restrict__ out)
{
    extern __shared__ float sm[];
    float* A   = sm;
    float* Wb  = sm + 128 * AS;
    float* wsv = Wb + 2 * 32 * WS;
    float* wrv = wsv + 128;

    int tid = threadIdx.x;
    int tx = tid & 15, ty = tid >> 4;
    int rowBlk = blockIdx.x * 128;
    const int wbase = tx * 8 + (tx >> 2) * 4;

    if (tid < 128) wsv[tid] = Wsig[tid];
    if (tid < 192) wrv[tid] = Wr[tid];

    // stage X block into A (row-major)
    {
        const float4* src = reinterpret_cast<const float4*>(g_X + (size_t)rowBlk * 128);
#pragma unroll
        for (int i = 0; i < 16; i++) {
            int f4 = tid + i * 256;
            float4 v = src[f4];
            int row = f4 >> 5, c4 = f4 & 31;
            *reinterpret_cast<float4*>(A + row * AS + c4 * 4) = v;
        }
    }

    const float* Wgs[6] = { g_W2xp, g_W0p, W1, g_W2hp, W3, Wf };
    const float* bgs[6] = { b0, b0, b1, b2, b3, bf };

    float sigR = 0.f;
    ull acc[8][4];

    for (int L = 0; L < 6; ++L) {
        const float* Wg = Wgs[L];
#pragma unroll
        for (int i = 0; i < 8; i++)
#pragma unroll
            for (int j = 0; j < 4; j++) acc[i][j] = 0ULL;

        // stage tile 0
#pragma unroll
        for (int i = 0; i < 4; i++) {
            float4 v = reinterpret_cast<const float4*>(Wg)[tid * 4 + i];
            int flat = tid * 16 + i * 4;
            int k = flat >> 7, col = flat & 127;
            *reinterpret_cast<float4*>(Wb + k * WS + wsw(col)) = v;
        }
        __syncthreads();

        for (int t = 0; t < 4; t++) {
            float4 pf[4];
            if (t < 3) {
                const float4* g = reinterpret_cast<const float4*>(Wg + (t + 1) * 4096);
#pragma unroll
                for (int i = 0; i < 4; i++) pf[i] = g[tid * 4 + i];
            }
            const float* Wt = Wb + (t & 1) * (32 * WS);
#pragma unroll
            for (int k4 = 0; k4 < 8; k4++) {
                float4 w0[4], w1[4];
#pragma unroll
                for (int kk = 0; kk < 4; kk++) {
                    const float* wp = Wt + (k4 * 4 + kk) * WS + wbase;
                    w0[kk] = *reinterpret_cast<const float4*>(wp);
                    w1[kk] = *reinterpret_cast<const float4*>(wp + 4);
                }
#pragma unroll
                for (int r4 = 0; r4 < 2; r4++) {
                    float4 ar[4];
#pragma unroll
                    for (int r = 0; r < 4; r++)
                        ar[r] = *reinterpret_cast<const float4*>(
                            A + (ty * 8 + r4 * 4 + r) * AS + t * 32 + k4 * 4);
#pragma unroll
                    for (int kk = 0; kk < 4; kk++) {
                        ull wp0 = pk2(w0[kk].x, w0[kk].y);
                        ull wp1 = pk2(w0[kk].z, w0[kk].w);
                        ull wp2 = pk2(w1[kk].x, w1[kk].y);
                        ull wp3 = pk2(w1[kk].z, w1[kk].w);
#pragma unroll
                        for (int r = 0; r < 4; r++) {
                            float av = (kk == 0) ? ar[r].x : (kk == 1) ? ar[r].y
                                     : (kk == 2) ? ar[r].z : ar[r].w;
                            ull ad = pk2(av, av);
                            int ri = r4 * 4 + r;
                            fma2(acc[ri][0], ad, wp0);
                            fma2(acc[ri][1], ad, wp1);
                            fma2(acc[ri][2], ad, wp2);
                            fma2(acc[ri][3], ad, wp3);
                        }
                    }
                }
            }
            if (t < 3) {
                float* d = Wb + ((t + 1) & 1) * (32 * WS);
#pragma unroll
                for (int i = 0; i < 4; i++) {
                    int flat = tid * 16 + i * 4;
                    int k = flat >> 7, col = flat & 127;
                    *reinterpret_cast<float4*>(d + k * WS + wsw(col)) = pf[i];
                }
            }
            __syncthreads();
        }

        // ---- epilogue / writeback ----
        if (L == 0) {
            // raw U -> global scratch (same thread re-reads same cells at L==3)
#pragma unroll
            for (int i = 0; i < 8; i++) {
                size_t row = (size_t)(rowBlk + ty * 8 + i);
                float o[8];
#pragma unroll
                for (int j = 0; j < 4; j++) {
                    float2 v = up2(acc[i][j]); o[2 * j] = v.x; o[2 * j + 1] = v.y;
                }
                *reinterpret_cast<float4*>(g_U + row * 128 + tx * 8) =
                    make_float4(o[0], o[1], o[2], o[3]);
                *reinterpret_cast<float4*>(g_U + row * 128 + tx * 8 + 4) =
                    make_float4(o[4], o[5], o[6], o[7]);
            }
        } else {
            const float* bg = bgs[L];
            float4 bA = *reinterpret_cast<const float4*>(bg + tx * 8);
            float4 bB = *reinterpret_cast<const float4*>(bg + tx * 8 + 4);
            bool relu = (L != 5);
#pragma unroll
            for (int i = 0; i < 8; i++) {
                int row = ty * 8 + i;
                float o[8];
#pragma unroll
                for (int j = 0; j < 4; j++) {
                    float2 v = up2(acc[i][j]); o[2 * j] = v.x; o[2 * j + 1] = v.y;
                }
                if (L == 3) {
                    size_t gr = (size_t)(rowBlk + row);
                    float4 u0 = *reinterpret_cast<const float4*>(g_U + gr * 128 + tx * 8);
                    float4 u1 = *reinterpret_cast<const float4*>(g_U + gr * 128 + tx * 8 + 4);
                    o[0] += u0.x; o[1] += u0.y; o[2] += u0.z; o[3] += u0.w;
                    o[4] += u1.x; o[5] += u1.y; o[6] += u1.z; o[7] += u1.w;
                }
                o[0] += bA.x; o[1] += bA.y; o[2] += bA.z; o[3] += bA.w;
                o[4] += bB.x; o[5] += bB.y; o[6] += bB.z; o[7] += bB.w;
                if (relu) {
#pragma unroll
                    for (int c = 0; c < 8; c++) o[c] = fmaxf(o[c], 0.f);
                }
                *reinterpret_cast<float4*>(A + row * AS + tx * 8) =
                    make_float4(o[0], o[1], o[2], o[3]);
                *reinterpret_cast<float4*>(A + row * AS + tx * 8 + 4) =
                    make_float4(o[4], o[5], o[6], o[7]);
            }
        }
        __syncthreads();

        if (L == 4 && tid < 128) {         // sigma from h (A) before Wf overwrites
            float s = 0.f;
#pragma unroll
            for (int k4 = 0; k4 < 32; k4++) {
                float4 hv = *reinterpret_cast<const float4*>(A + tid * AS + k4 * 4);
                s = fmaf(hv.x, wsv[k4 * 4 + 0], s);
                s = fmaf(hv.y, wsv[k4 * 4 + 1], s);
                s = fmaf(hv.z, wsv[k4 * 4 + 2], s);
                s = fmaf(hv.w, wsv[k4 * 4 + 3], s);
            }
            sigR = s + bs[0];
        }
    }

    // ---- dir layer: d = relu(final @ Wdf + V), 64 cols, K=128 -------------
    int tx8 = tid & 7, ty32 = tid >> 3;
    const int wb64 = tx8 * 8 + (tx8 >> 2) * 4;
    ull acc2[4][4];
#pragma unroll
    for (int i = 0; i < 4; i++)
#pragma unroll
        for (int j = 0; j < 4; j++) acc2[i][j] = 0ULL;

#pragma unroll
    for (int i = 0; i < 2; i++) {          // stage tile 0 (32x64)
        float4 v = reinterpret_cast<const float4*>(g_Wdfp)[tid * 2 + i];
        int flat = tid * 8 + i * 4;
        int k = flat >> 6, col = flat & 63;
        *reinterpret_cast<float4*>(Wb + k * WS + wsw(col)) = v;
    }
    __syncthreads();

    for (int t = 0; t < 4; t++) {
        float4 pf[2];
        if (t < 3) {
            const float4* g = reinterpret_cast<const float4*>(g_Wdfp + (t + 1) * 2048);
#pragma unroll
            for (int i = 0; i < 2; i++) pf[i] = g[tid * 2 + i];
        }
        const float* Wt = Wb + (t & 1) * (32 * WS);
#pragma unroll
        for (int k4 = 0; k4 < 8; k4++) {
            float4 w0[4], w1[4];
#pragma unroll
            for (int kk = 0; kk < 4; kk++) {
                const float* wp = Wt + (k4 * 4 + kk) * WS + wb64;
                w0[kk] = *reinterpret_cast<const float4*>(wp);
                w1[kk] = *reinterpret_cast<const float4*>(wp + 4);
            }
            float4 ar[4];
#pragma unroll
            for (int r = 0; r < 4; r++)
                ar[r] = *reinterpret_cast<const float4*>(
                    A + (ty32 * 4 + r) * AS + t * 32 + k4 * 4);
#pragma unroll
            for (int kk = 0; kk < 4; kk++) {
                ull wp0 = pk2(w0[kk].x, w0[kk].y);
                ull wp1 = pk2(w0[kk].z, w0[kk].w);
                ull wp2 = pk2(w1[kk].x, w1[kk].y);
                ull wp3 = pk2(w1[kk].z, w1[kk].w);
#pragma unroll
                for (int r = 0; r < 4; r++) {
                    float av = (kk == 0) ? ar[r].x : (kk == 1) ? ar[r].y
                             : (kk == 2) ? ar[r].z : ar[r].w;
                    ull ad = pk2(av, av);
                    fma2(acc2[r][0], ad, wp0);
                    fma2(acc2[r][1], ad, wp1);
                    fma2(acc2[r][2], ad, wp2);
                    fma2(acc2[r][3], ad, wp3);
                }
            }
        }
        if (t < 3) {
            float* d = Wb + ((t + 1) & 1) * (32 * WS);
#pragma unroll
            for (int i = 0; i < 2; i++) {
                int flat = tid * 8 + i * 4;
                int k = flat >> 6, col = flat & 63;
                *reinterpret_cast<float4*>(d + k * WS + wsw(col)) = pf[i];
            }
        }
        __syncthreads();
    }

    // writeback d -> A (cols 0..63) with V + relu
#pragma unroll
    for (int r = 0; r < 4; r++) {
        int row = ty32 * 4 + r;
        size_t gr = (size_t)(rowBlk + row);
        float4 v0 = *reinterpret_cast<const float4*>(g_V + gr * 64 + tx8 * 8);
        float4 v1 = *reinterpret_cast<const float4*>(g_V + gr * 64 + tx8 * 8 + 4);
        float o[8];
#pragma unroll
        for (int j = 0; j < 4; j++) {
            float2 v = up2(acc2[r][j]); o[2 * j] = v.x; o[2 * j + 1] = v.y;
        }
        o[0] += v0.x; o[1] += v0.y; o[2] += v0.z; o[3] += v0.w;
        o[4] += v1.x; o[5] += v1.y; o[6] += v1.z; o[7] += v1.w;
#pragma unroll
        for (int c = 0; c < 8; c++) o[c] = fmaxf(o[c], 0.f);
        *reinterpret_cast<float4*>(A + row * AS + tx8 * 8) =
            make_float4(o[0], o[1], o[2], o[3]);
        *reinterpret_cast<float4*>(A + row * AS + tx8 * 8 + 4) =
            make_float4(o[4], o[5], o[6], o[7]);
    }
    __syncthreads();

    // rgb + output
    if (tid < 128) {
        float r0 = br[0], r1 = br[1], r2 = br[2];
#pragma unroll
        for (int k4 = 0; k4 < 16; k4++) {
            float4 dv = *reinterpret_cast<const float4*>(A + tid * AS + k4 * 4);
            const float* wr0 = wrv + k4 * 12;
            r0 = fmaf(dv.x, wr0[0], r0); r1 = fmaf(dv.x, wr0[1], r1); r2 = fmaf(dv.x, wr0[2], r2);
            r0 = fmaf(dv.y, wr0[3], r0); r1 = fmaf(dv.y, wr0[4], r1); r2 = fmaf(dv.y, wr0[5], r2);
            r0 = fmaf(dv.z, wr0[6], r0); r1 = fmaf(dv.z, wr0[7], r1); r2 = fmaf(dv.z, wr0[8], r2);
            r0 = fmaf(dv.w, wr0[9], r0); r1 = fmaf(dv.w, wr0[10], r1); r2 = fmaf(dv.w, wr0[11], r2);
        }
        *reinterpret_cast<float4*>(out + (size_t)(rowBlk + tid) * 4) =
            make_float4(r0, r1, r2, sigR);
    }
}

// ---------------------------------------------------------------------------
extern "C" void kernel_launch(void* const* d_in, const int* in_sizes, int n_in,
                              void* d_out, int out_size) {
    const int*   indices = (const int*)  d_in[0];
    const float* qp      = (const float*)d_in[1];
    const float* xyzdir  = (const float*)d_in[2];
    const float* cpos    = (const float*)d_in[3];
    const float* codes   = (const float*)d_in[4];
    const float* W0 = (const float*)d_in[5],  *b0 = (const float*)d_in[6];
    const float* W1 = (const float*)d_in[7],  *b1 = (const float*)d_in[8];
    const float* W2 = (const float*)d_in[9],  *b2 = (const float*)d_in[10];
    const float* W3 = (const float*)d_in[11], *b3 = (const float*)d_in[12];
    const float* Wf = (const float*)d_in[13], *bf = (const float*)d_in[14];
    const float* Wd = (const float*)d_in[15], *bd = (const float*)d_in[16];
    const float* Ws = (const float*)d_in[17], *bs = (const float*)d_in[18];
    const float* Wr = (const float*)d_in[19], *br = (const float*)d_in[20];
    float* out = (float*)d_out;

    const int smemBytes = SMEM_FLOATS * 4;
    cudaFuncSetAttribute(fused_mlp, cudaFuncAttributeMaxDynamicSharedMemorySize,
                         smemBytes);

    prep_weights<<<224, 256>>>(W0, W2, Wd);
    pack_inputs<<<1024, 256>>>(xyzdir);
    vcomp<<<NQ * 16 / 256, 256>>>(Wd, bd);
    knn_interp<<<NQ / 128, 128>>>(indices, qp, cpos, codes);
    fused_mlp<<<NQ / 128, 256, smemBytes>>>(W1, W3, Wf, b0, b1, b2, b3, bf,
                                            Ws, bs, Wr, br, out);
}

// round 6
// speedup vs baseline: 1.4943x; 1.1701x over previous
#include <cuda_runtime.h>
#include <cstdint>

#define NQ 65536
#define NC 2048
#define AS 132   // activation smem row stride (floats)
#define WS 144   // weight-tile smem row stride (floats)

typedef unsigned long long ull;

// ------- device scratch (static __device__ globals: allocation-free) -------
__device__ float g_X[NQ * 128];    // [query_codes 64 | xyz_emb 63 | 0]
__device__ float g_DIR[NQ * 32];   // [dir_emb 27 | 0 x5]
__device__ float g_U[NQ * 128];    // X @ W2x   (skip-path partial)
__device__ float g_V[NQ * 64];     // dir @ Wd_dir + bd
__device__ float g_WI[NQ * 32];    // per query: 16 x {w, idx-as-float}
__device__ int   g_hist[4096];
__device__ int   g_offs[4096];
__device__ int   g_perm[NQ];
__device__ float g_W0p[128 * 128];
__device__ float g_W2xp[128 * 128];
__device__ float g_W2hp[128 * 128];
__device__ float g_Wdfp[128 * 64];

// ------------------------- f32x2 helpers -----------------------------------
__device__ __forceinline__ ull pk2(float lo, float hi) {
    ull r; asm("mov.b64 %0,{%1,%2};" : "=l"(r) : "f"(lo), "f"(hi)); return r;
}
__device__ __forceinline__ void fma2(ull& c, ull a, ull b) {
    asm("fma.rn.f32x2 %0,%1,%2,%0;" : "+l"(c) : "l"(a), "l"(b));
}
__device__ __forceinline__ float2 up2(ull v) {
    float2 r; asm("mov.b64 {%0,%1},%2;" : "=f"(r.x), "=f"(r.y) : "l"(v)); return r;
}
__device__ __forceinline__ int wsw(int col) {
    int g = col >> 3;
    return g * 8 + (g >> 2) * 4 + (col & 7);
}
__device__ __forceinline__ int cell_of(float x, float y, float z) {
    int ix = min(15, max(0, (int)(x * 16.f)));
    int iy = min(15, max(0, (int)(y * 16.f)));
    int iz = min(15, max(0, (int)(z * 16.f)));
    return (ix << 8) | (iy << 4) | iz;
}

// --------------------- spatial counting sort of queries --------------------
__global__ void zero_hist() { g_hist[blockIdx.x * 256 + threadIdx.x] = 0; }

__global__ void hist_k(const float* __restrict__ qp) {
    int q = blockIdx.x * 256 + threadIdx.x;
    atomicAdd(&g_hist[cell_of(qp[3 * q], qp[3 * q + 1], qp[3 * q + 2])], 1);
}

__global__ void __launch_bounds__(1024) scan_k() {   // 1 block
    __shared__ int s[1024];
    int tid = threadIdx.x;
    int v[4]; int sum = 0;
#pragma unroll
    for (int i = 0; i < 4; i++) { v[i] = g_hist[tid * 4 + i]; sum += v[i]; }
    s[tid] = sum; __syncthreads();
    for (int off = 1; off < 1024; off <<= 1) {
        int t = (tid >= off) ? s[tid - off] : 0;
        __syncthreads();
        s[tid] += t;
        __syncthreads();
    }
    int run = tid ? s[tid - 1] : 0;
#pragma unroll
    for (int i = 0; i < 4; i++) { g_offs[tid * 4 + i] = run; run += v[i]; }
}

__global__ void scatter_k(const float* __restrict__ qp) {
    int q = blockIdx.x * 256 + threadIdx.x;
    int cell = cell_of(qp[3 * q], qp[3 * q + 1], qp[3 * q + 2]);
    int pos = atomicAdd(&g_offs[cell], 1);
    g_perm[pos] = q;
}

// ------------------------- weight prep -------------------------------------
__global__ void prep_weights(const float* __restrict__ W0,
                             const float* __restrict__ W2,
                             const float* __restrict__ Wd) {
    const int T0 = 16384, T1 = 16384, T2 = 16384, T3 = 8192;
    int total = T0 + T1 + T2 + T3;
    for (int i = blockIdx.x * blockDim.x + threadIdx.x; i < total;
         i += gridDim.x * blockDim.x) {
        if (i < T0) {
            int r = i >> 7, c = i & 127;
            g_W0p[i] = (r < 127) ? W0[r * 128 + c] : 0.f;
        } else if (i < T0 + T1) {
            int j = i - T0; int r = j >> 7, c = j & 127;
            g_W2xp[j] = (r < 127) ? W2[r * 128 + c] : 0.f;
        } else if (i < T0 + T1 + T2) {
            int j = i - T0 - T1; int r = j >> 7, c = j & 127;
            g_W2hp[j] = W2[(127 + r) * 128 + c];
        } else {
            int j = i - T0 - T1 - T2;
            g_Wdfp[j] = Wd[j];
        }
    }
}

// --------------------- pack xyz / dir embeddings ---------------------------
__global__ void pack_inputs(const float* __restrict__ xyzdir) {
    const int TA = NQ * 64;
    const int total = NQ * 64 + NQ * 32;
    for (int i = blockIdx.x * blockDim.x + threadIdx.x; i < total;
         i += gridDim.x * blockDim.x) {
        if (i < TA) {
            int q = i >> 6, e = i & 63;
            g_X[q * 128 + 64 + e] = (e < 63) ? xyzdir[q * 90 + e] : 0.f;
        } else {
            int j = i - TA; int q = j >> 5, e = j & 31;
            g_DIR[j] = (e < 27) ? xyzdir[q * 90 + 63 + e] : 0.f;
        }
    }
}

// ---------------- V = dir @ Wd[128:155] + bd  ------------------------------
__global__ void __launch_bounds__(256) vcomp(const float* __restrict__ Wd,
                                             const float* __restrict__ bd) {
    __shared__ float sw[27 * 64];
    __shared__ float sb[64];
    int tid = threadIdx.x;
    for (int i = tid; i < 27 * 64; i += 256) sw[i] = Wd[128 * 64 + i];
    if (tid < 64) sb[tid] = bd[tid];
    __syncthreads();
    int idx = blockIdx.x * 256 + tid;
    int q = idx >> 4, c0 = (idx & 15) * 4;
    float a0 = sb[c0], a1 = sb[c0 + 1], a2 = sb[c0 + 2], a3 = sb[c0 + 3];
#pragma unroll
    for (int k = 0; k < 27; k++) {
        float dv = g_DIR[q * 32 + k];
        a0 = fmaf(dv, sw[k * 64 + c0 + 0], a0);
        a1 = fmaf(dv, sw[k * 64 + c0 + 1], a1);
        a2 = fmaf(dv, sw[k * 64 + c0 + 2], a2);
        a3 = fmaf(dv, sw[k * 64 + c0 + 3], a3);
    }
    *reinterpret_cast<float4*>(g_V + (size_t)q * 64 + c0) = make_float4(a0, a1, a2, a3);
}

// --------------- KNN(16): clustered queries, fma-pipe scan -----------------
__global__ void __launch_bounds__(128) knn_sel(const int* __restrict__ indices,
                                               const float* __restrict__ qp,
                                               const float* __restrict__ cpos) {
    __shared__ float4 sp[NC];      // {x, y, z, ||c||^2}
    int tid = threadIdx.x;
    int ib = indices[0];
    const float* cp = cpos + (size_t)ib * NC * 3;
    for (int c = tid; c < NC; c += 128) {
        float x = cp[c * 3 + 0], y = cp[c * 3 + 1], z = cp[c * 3 + 2];
        sp[c] = make_float4(x, y, z, fmaf(x, x, fmaf(y, y, z * z)));
    }
    __syncthreads();

    int q = g_perm[blockIdx.x * 128 + tid];
    float qx = qp[q * 3 + 0], qy = qp[q * 3 + 1], qz = qp[q * 3 + 2];
    float qx2 = -2.f * qx, qy2 = -2.f * qy, qz2 = -2.f * qz;
    float q2 = fmaf(qx, qx, fmaf(qy, qy, qz * qz));

    unsigned bk[16];
#pragma unroll
    for (int j = 0; j < 16; j++) bk[j] = 0x7F7FFFFFu;
    float bnd = __uint_as_float(0x7F7FF800u) - q2;   // d2' threshold

    for (int c = 0; c < NC; c += 4) {
#pragma unroll
        for (int i = 0; i < 4; i++) {
            float4 v = sp[c + i];
            float dp = fmaf(v.x, qx2, fmaf(v.y, qy2, fmaf(v.z, qz2, v.w)));
            if (dp < bnd) {
                float dfull = fmaxf(dp + q2, 0.f);   // clamp: keep bits ordered
                unsigned cur = (__float_as_uint(dfull) & 0xFFFFF800u)
                             | (unsigned)(c + i);
#pragma unroll
                for (int j = 0; j < 16; j++) {
                    unsigned mn = min(bk[j], cur);
                    unsigned mx = max(bk[j], cur);
                    bk[j] = mn; cur = mx;
                }
                bnd = __uint_as_float(bk[15] & 0xFFFFF800u) - q2;
            }
        }
    }

    // exact distances -> normalized 1/d2 weights
    float w[16]; int ci[16]; float wsum = 0.f;
#pragma unroll
    for (int k = 0; k < 16; k++) {
        int c = (int)(bk[k] & 0x7FFu); ci[k] = c;
        float4 v = sp[c];
        float dx = qx - v.x, dy = qy - v.y, dz = qz - v.z;
        float d2 = fmaf(dx, dx, fmaf(dy, dy, dz * dz)) + 1e-16f;
        w[k] = 1.0f / d2; wsum += w[k];
    }
    float inv = 1.0f / wsum;
#pragma unroll
    for (int k = 0; k < 16; k += 2) {
        *reinterpret_cast<float4*>(g_WI + (size_t)q * 32 + k * 2) =
            make_float4(w[k] * inv, __int_as_float(ci[k]),
                        w[k + 1] * inv, __int_as_float(ci[k + 1]));
    }
}

// --------------- weighted code interpolation (gather) ----------------------
__global__ void __launch_bounds__(128) interp_k(const int* __restrict__ indices,
                                                const float* __restrict__ codes) {
    int tid = threadIdx.x;
    int ib = indices[0];
    const float* cc = codes + (size_t)ib * NC * 64;
    int lane = tid & 31;
    int base = blockIdx.x * 128 + (tid & ~31);
    for (int s = 0; s < 32; s++) {
        int t = base + s;
        const float2* wi = reinterpret_cast<const float2*>(g_WI) + (size_t)t * 16;
        float a0 = 0.f, a1 = 0.f;
#pragma unroll
        for (int k = 0; k < 16; k++) {
            float2 p = wi[k];                       // broadcast load
            const float* row = cc + __float_as_int(p.y) * 64;
            a0 = fmaf(p.x, row[lane], a0);
            a1 = fmaf(p.x, row[lane + 32], a1);
        }
        g_X[(size_t)t * 128 + lane] = a0;
        g_X[(size_t)t * 128 + 32 + lane] = a1;
    }
}

// ===================== fused MLP (entire network) ==========================
#define SMEM_FLOATS (128 * AS + 2 * 32 * WS + 128 + 192)

__global__ void __launch_bounds__(256, 2) fused_mlp(
    const float* __restrict__ W1, const float* __restrict__ W3,
    const float* __restrict__ Wf,
    const float* __restrict__ b0, const float* __restrict__ b1,
    const float* __restrict__ b2, const float* __restrict__ b3,
    const float* __restrict__ bf,
    const float* __restrict__ Wsig, const float* __restrict__ bs,
    const float* __restrict__ Wr,   const float* __restrict__ br,
    float* __restrict__ out)
{
    extern __shared__ float sm[];
    float* A   = sm;
    float* Wb  = sm + 128 * AS;
    float* wsv = Wb + 2 * 32 * WS;
    float* wrv = wsv + 128;

    int tid = threadIdx.x;
    int tx = tid & 15, ty = tid >> 4;
    int rowBlk = blockIdx.x * 128;
    const int wbase = tx * 8 + (tx >> 2) * 4;

    if (tid < 128) wsv[tid] = Wsig[tid];
    if (tid < 192) wrv[tid] = Wr[tid];

    {
        const float4* src = reinterpret_cast<const float4*>(g_X + (size_t)rowBlk * 128);
#pragma unroll
        for (int i = 0; i < 16; i++) {
            int f4 = tid + i * 256;
            float4 v = src[f4];
            int row = f4 >> 5, c4 = f4 & 31;
            *reinterpret_cast<float4*>(A + row * AS + c4 * 4) = v;
        }
    }

    const float* Wgs[6] = { g_W2xp, g_W0p, W1, g_W2hp, W3, Wf };
    const float* bgs[6] = { b0, b0, b1, b2, b3, bf };

    float sigR = 0.f;
    ull acc[8][4];

    for (int L = 0; L < 6; ++L) {
        const float* Wg = Wgs[L];
#pragma unroll
        for (int i = 0; i < 8; i++)
#pragma unroll
            for (int j = 0; j < 4; j++) acc[i][j] = 0ULL;

#pragma unroll
        for (int i = 0; i < 4; i++) {
            float4 v = reinterpret_cast<const float4*>(Wg)[tid * 4 + i];
            int flat = tid * 16 + i * 4;
            int k = flat >> 7, col = flat & 127;
            *reinterpret_cast<float4*>(Wb + k * WS + wsw(col)) = v;
        }
        __syncthreads();

        for (int t = 0; t < 4; t++) {
            float4 pf[4];
            if (t < 3) {
                const float4* g = reinterpret_cast<const float4*>(Wg + (t + 1) * 4096);
#pragma unroll
                for (int i = 0; i < 4; i++) pf[i] = g[tid * 4 + i];
            }
            const float* Wt = Wb + (t & 1) * (32 * WS);
#pragma unroll
            for (int k4 = 0; k4 < 8; k4++) {
                float4 w0[4], w1[4];
#pragma unroll
                for (int kk = 0; kk < 4; kk++) {
                    const float* wp = Wt + (k4 * 4 + kk) * WS + wbase;
                    w0[kk] = *reinterpret_cast<const float4*>(wp);
                    w1[kk] = *reinterpret_cast<const float4*>(wp + 4);
                }
#pragma unroll
                for (int r4 = 0; r4 < 2; r4++) {
                    float4 ar[4];
#pragma unroll
                    for (int r = 0; r < 4; r++)
                        ar[r] = *reinterpret_cast<const float4*>(
                            A + (ty * 8 + r4 * 4 + r) * AS + t * 32 + k4 * 4);
#pragma unroll
                    for (int kk = 0; kk < 4; kk++) {
                        ull wp0 = pk2(w0[kk].x, w0[kk].y);
                        ull wp1 = pk2(w0[kk].z, w0[kk].w);
                        ull wp2 = pk2(w1[kk].x, w1[kk].y);
                        ull wp3 = pk2(w1[kk].z, w1[kk].w);
#pragma unroll
                        for (int r = 0; r < 4; r++) {
                            float av = (kk == 0) ? ar[r].x : (kk == 1) ? ar[r].y
                                     : (kk == 2) ? ar[r].z : ar[r].w;
                            ull ad = pk2(av, av);
                            int ri = r4 * 4 + r;
                            fma2(acc[ri][0], ad, wp0);
                            fma2(acc[ri][1], ad, wp1);
                            fma2(acc[ri][2], ad, wp2);
                            fma2(acc[ri][3], ad, wp3);
                        }
                    }
                }
            }
            if (t < 3) {
                float* d = Wb + ((t + 1) & 1) * (32 * WS);
#pragma unroll
                for (int i = 0; i < 4; i++) {
                    int flat = tid * 16 + i * 4;
                    int k = flat >> 7, col = flat & 127;
                    *reinterpret_cast<float4*>(d + k * WS + wsw(col)) = pf[i];
                }
            }
            __syncthreads();
        }

        if (L == 0) {
#pragma unroll
            for (int i = 0; i < 8; i++) {
                size_t row = (size_t)(rowBlk + ty * 8 + i);
                float o[8];
#pragma unroll
                for (int j = 0; j < 4; j++) {
                    float2 v = up2(acc[i][j]); o[2 * j] = v.x; o[2 * j + 1] = v.y;
                }
                *reinterpret_cast<float4*>(g_U + row * 128 + tx * 8) =
                    make_float4(o[0], o[1], o[2], o[3]);
                *reinterpret_cast<float4*>(g_U + row * 128 + tx * 8 + 4) =
                    make_float4(o[4], o[5], o[6], o[7]);
            }
        } else {
            const float* bg = bgs[L];
            float4 bA = *reinterpret_cast<const float4*>(bg + tx * 8);
            float4 bB = *reinterpret_cast<const float4*>(bg + tx * 8 + 4);
            bool relu = (L != 5);
#pragma unroll
            for (int i = 0; i < 8; i++) {
                int row = ty * 8 + i;
                float o[8];
#pragma unroll
                for (int j = 0; j < 4; j++) {
                    float2 v = up2(acc[i][j]); o[2 * j] = v.x; o[2 * j + 1] = v.y;
                }
                if (L == 3) {
                    size_t gr = (size_t)(rowBlk + row);
                    float4 u0 = *reinterpret_cast<const float4*>(g_U + gr * 128 + tx * 8);
                    float4 u1 = *reinterpret_cast<const float4*>(g_U + gr * 128 + tx * 8 + 4);
                    o[0] += u0.x; o[1] += u0.y; o[2] += u0.z; o[3] += u0.w;
                    o[4] += u1.x; o[5] += u1.y; o[6] += u1.z; o[7] += u1.w;
                }
                o[0] += bA.x; o[1] += bA.y; o[2] += bA.z; o[3] += bA.w;
                o[4] += bB.x; o[5] += bB.y; o[6] += bB.z; o[7] += bB.w;
                if (relu) {
#pragma unroll
                    for (int c = 0; c < 8; c++) o[c] = fmaxf(o[c], 0.f);
                }
                *reinterpret_cast<float4*>(A + row * AS + tx * 8) =
                    make_float4(o[0], o[1], o[2], o[3]);
                *reinterpret_cast<float4*>(A + row * AS + tx * 8 + 4) =
                    make_float4(o[4], o[5], o[6], o[7]);
            }
        }
        __syncthreads();

        if (L == 4 && tid < 128) {
            float s = 0.f;
#pragma unroll
            for (int k4 = 0; k4 < 32; k4++) {
                float4 hv = *reinterpret_cast<const float4*>(A + tid * AS + k4 * 4);
                s = fmaf(hv.x, wsv[k4 * 4 + 0], s);
                s = fmaf(hv.y, wsv[k4 * 4 + 1], s);
                s = fmaf(hv.z, wsv[k4 * 4 + 2], s);
                s = fmaf(hv.w, wsv[k4 * 4 + 3], s);
            }
            sigR = s + bs[0];
        }
    }

    // ---- dir layer ----
    int tx8 = tid & 7, ty32 = tid >> 3;
    const int wb64 = tx8 * 8 + (tx8 >> 2) * 4;
    ull acc2[4][4];
#pragma unroll
    for (int i = 0; i < 4; i++)
#pragma unroll
        for (int j = 0; j < 4; j++) acc2[i][j] = 0ULL;

#pragma unroll
    for (int i = 0; i < 2; i++) {
        float4 v = reinterpret_cast<const float4*>(g_Wdfp)[tid * 2 + i];
        int flat = tid * 8 + i * 4;
        int k = flat >> 6, col = flat & 63;
        *reinterpret_cast<float4*>(Wb + k * WS + wsw(col)) = v;
    }
    __syncthreads();

    for (int t = 0; t < 4; t++) {
        float4 pf[2];
        if (t < 3) {
            const float4* g = reinterpret_cast<const float4*>(g_Wdfp + (t + 1) * 2048);
#pragma unroll
            for (int i = 0; i < 2; i++) pf[i] = g[tid * 2 + i];
        }
        const float* Wt = Wb + (t & 1) * (32 * WS);
#pragma unroll
        for (int k4 = 0; k4 < 8; k4++) {
            float4 w0[4], w1[4];
#pragma unroll
            for (int kk = 0; kk < 4; kk++) {
                const float* wp = Wt + (k4 * 4 + kk) * WS + wb64;
                w0[kk] = *reinterpret_cast<const float4*>(wp);
                w1[kk] = *reinterpret_cast<const float4*>(wp + 4);
            }
            float4 ar[4];
#pragma unroll
            for (int r = 0; r < 4; r++)
                ar[r] = *reinterpret_cast<const float4*>(
                    A + (ty32 * 4 + r) * AS + t * 32 + k4 * 4);
#pragma unroll
            for (int kk = 0; kk < 4; kk++) {
                ull wp0 = pk2(w0[kk].x, w0[kk].y);
                ull wp1 = pk2(w0[kk].z, w0[kk].w);
                ull wp2 = pk2(w1[kk].x, w1[kk].y);
                ull wp3 = pk2(w1[kk].z, w1[kk].w);
#pragma unroll
                for (int r = 0; r < 4; r++) {
                    float av = (kk == 0) ? ar[r].x : (kk == 1) ? ar[r].y
                             : (kk == 2) ? ar[r].z : ar[r].w;
                    ull ad = pk2(av, av);
                    fma2(acc2[r][0], ad, wp0);
                    fma2(acc2[r][1], ad, wp1);
                    fma2(acc2[r][2], ad, wp2);
                    fma2(acc2[r][3], ad, wp3);
                }
            }
        }
        if (t < 3) {
            float* d = Wb + ((t + 1) & 1) * (32 * WS);
#pragma unroll
            for (int i = 0; i < 2; i++) {
                int flat = tid * 8 + i * 4;
                int k = flat >> 6, col = flat & 63;
                *reinterpret_cast<float4*>(d + k * WS + wsw(col)) = pf[i];
            }
        }
        __syncthreads();
    }

#pragma unroll
    for (int r = 0; r < 4; r++) {
        int row = ty32 * 4 + r;
        size_t gr = (size_t)(rowBlk + row);
        float4 v0 = *reinterpret_cast<const float4*>(g_V + gr * 64 + tx8 * 8);
        float4 v1 = *reinterpret_cast<const float4*>(g_V + gr * 64 + tx8 * 8 + 4);
        float o[8];
#pragma unroll
        for (int j = 0; j < 4; j++) {
            float2 v = up2(acc2[r][j]); o[2 * j] = v.x; o[2 * j + 1] = v.y;
        }
        o[0] += v0.x; o[1] += v0.y; o[2] += v0.z; o[3] += v0.w;
        o[4] += v1.x; o[5] += v1.y; o[6] += v1.z; o[7] += v1.w;
#pragma unroll
        for (int c = 0; c < 8; c++) o[c] = fmaxf(o[c], 0.f);
        *reinterpret_cast<float4*>(A + row * AS + tx8 * 8) =
            make_float4(o[0], o[1], o[2], o[3]);
        *reinterpret_cast<float4*>(A + row * AS + tx8 * 8 + 4) =
            make_float4(o[4], o[5], o[6], o[7]);
    }
    __syncthreads();

    if (tid < 128) {
        float r0 = br[0], r1 = br[1], r2 = br[2];
#pragma unroll
        for (int k4 = 0; k4 < 16; k4++) {
            float4 dv = *reinterpret_cast<const float4*>(A + tid * AS + k4 * 4);
            const float* wr0 = wrv + k4 * 12;
            r0 = fmaf(dv.x, wr0[0], r0); r1 = fmaf(dv.x, wr0[1], r1); r2 = fmaf(dv.x, wr0[2], r2);
            r0 = fmaf(dv.y, wr0[3], r0); r1 = fmaf(dv.y, wr0[4], r1); r2 = fmaf(dv.y, wr0[5], r2);
            r0 = fmaf(dv.z, wr0[6], r0); r1 = fmaf(dv.z, wr0[7], r1); r2 = fmaf(dv.z, wr0[8], r2);
            r0 = fmaf(dv.w, wr0[9], r0); r1 = fmaf(dv.w, wr0[10], r1); r2 = fmaf(dv.w, wr0[11], r2);
        }
        *reinterpret_cast<float4*>(out + (size_t)(rowBlk + tid) * 4) =
            make_float4(r0, r1, r2, sigR);
    }
}

// ---------------------------------------------------------------------------
extern "C" void kernel_launch(void* const* d_in, const int* in_sizes, int n_in,
                              void* d_out, int out_size) {
    const int*   indices = (const int*)  d_in[0];
    const float* qp      = (const float*)d_in[1];
    const float* xyzdir  = (const float*)d_in[2];
    const float* cpos    = (const float*)d_in[3];
    const float* codes   = (const float*)d_in[4];
    const float* W0 = (const float*)d_in[5],  *b0 = (const float*)d_in[6];
    const float* W1 = (const float*)d_in[7],  *b1 = (const float*)d_in[8];
    const float* W2 = (const float*)d_in[9],  *b2 = (const float*)d_in[10];
    const float* W3 = (const float*)d_in[11], *b3 = (const float*)d_in[12];
    const float* Wf = (const float*)d_in[13], *bf = (const float*)d_in[14];
    const float* Wd = (const float*)d_in[15], *bd = (const float*)d_in[16];
    const float* Ws = (const float*)d_in[17], *bs = (const float*)d_in[18];
    const float* Wr = (const float*)d_in[19], *br = (const float*)d_in[20];
    float* out = (float*)d_out;

    const int smemBytes = SMEM_FLOATS * 4;
    cudaFuncSetAttribute(fused_mlp, cudaFuncAttributeMaxDynamicSharedMemorySize,
                         smemBytes);

    zero_hist<<<16, 256>>>();
    hist_k<<<NQ / 256, 256>>>(qp);
    scan_k<<<1, 1024>>>();
    scatter_k<<<NQ / 256, 256>>>(qp);
    prep_weights<<<224, 256>>>(W0, W2, Wd);
    pack_inputs<<<1024, 256>>>(xyzdir);
    vcomp<<<NQ * 16 / 256, 256>>>(Wd, bd);
    knn_sel<<<NQ / 128, 128>>>(indices, qp, cpos);
    interp_k<<<NQ / 128, 128>>>(indices, codes);
    fused_mlp<<<NQ / 128, 256, smemBytes>>>(W1, W3, Wf, b0, b1, b2, b3, bf,
                                            Ws, bs, Wr, br, out);
}

// round 7
// speedup vs baseline: 1.5749x; 1.0539x over previous
#include <cuda_runtime.h>
#include <cstdint>

#define NQ 65536
#define NC 2048
#define AS 132   // activation smem row stride (floats)
#define WS 144   // weight-tile smem row stride (floats)

typedef unsigned long long ull;

// ------- device scratch (static __device__ globals: allocation-free) -------
__device__ float g_X[NQ * 128];    // [query_codes 64 | xyz_emb 63 | 0]
__device__ float g_DIR[NQ * 32];   // [dir_emb 27 | 0 x5]
__device__ float g_U[NQ * 128];    // X @ W2x   (skip-path partial)
__device__ float g_V[NQ * 64];     // dir @ Wd_dir + bd
__device__ int   g_hist[4096];
__device__ int   g_offs[4096];
__device__ int   g_perm[NQ];
__device__ float g_W0p[128 * 128];
__device__ float g_W2xp[128 * 128];
__device__ float g_W2hp[128 * 128];
__device__ float g_Wdfp[128 * 64];

// ------------------------- f32x2 helpers -----------------------------------
__device__ __forceinline__ ull pk2(float lo, float hi) {
    ull r; asm("mov.b64 %0,{%1,%2};" : "=l"(r) : "f"(lo), "f"(hi)); return r;
}
__device__ __forceinline__ void fma2(ull& c, ull a, ull b) {
    asm("fma.rn.f32x2 %0,%1,%2,%0;" : "+l"(c) : "l"(a), "l"(b));
}
__device__ __forceinline__ float2 up2(ull v) {
    float2 r; asm("mov.b64 {%0,%1},%2;" : "=f"(r.x), "=f"(r.y) : "l"(v)); return r;
}
__device__ __forceinline__ int wsw(int col) {
    int g = col >> 3;
    return g * 8 + (g >> 2) * 4 + (col & 7);
}
__device__ __forceinline__ int cell_of(float x, float y, float z) {
    int ix = min(15, max(0, (int)(x * 16.f)));
    int iy = min(15, max(0, (int)(y * 16.f)));
    int iz = min(15, max(0, (int)(z * 16.f)));
    return (ix << 8) | (iy << 4) | iz;
}

// --------------------- spatial counting sort of queries --------------------
__global__ void zero_hist() { g_hist[blockIdx.x * 256 + threadIdx.x] = 0; }

__global__ void hist_k(const float* __restrict__ qp) {
    int q = blockIdx.x * 256 + threadIdx.x;
    atomicAdd(&g_hist[cell_of(qp[3 * q], qp[3 * q + 1], qp[3 * q + 2])], 1);
}

__global__ void __launch_bounds__(1024) scan_k() {   // 1 block
    __shared__ int s[1024];
    int tid = threadIdx.x;
    int v[4]; int sum = 0;
#pragma unroll
    for (int i = 0; i < 4; i++) { v[i] = g_hist[tid * 4 + i]; sum += v[i]; }
    s[tid] = sum; __syncthreads();
    for (int off = 1; off < 1024; off <<= 1) {
        int t = (tid >= off) ? s[tid - off] : 0;
        __syncthreads();
        s[tid] += t;
        __syncthreads();
    }
    int run = tid ? s[tid - 1] : 0;
#pragma unroll
    for (int i = 0; i < 4; i++) { g_offs[tid * 4 + i] = run; run += v[i]; }
}

__global__ void scatter_k(const float* __restrict__ qp) {
    int q = blockIdx.x * 256 + threadIdx.x;
    int cell = cell_of(qp[3 * q], qp[3 * q + 1], qp[3 * q + 2]);
    int pos = atomicAdd(&g_offs[cell], 1);
    g_perm[pos] = q;
}

// ------------------------- weight prep -------------------------------------
__global__ void prep_weights(const float* __restrict__ W0,
                             const float* __restrict__ W2,
                             const float* __restrict__ Wd) {
    const int T0 = 16384, T1 = 16384, T2 = 16384, T3 = 8192;
    int total = T0 + T1 + T2 + T3;
    for (int i = blockIdx.x * blockDim.x + threadIdx.x; i < total;
         i += gridDim.x * blockDim.x) {
        if (i < T0) {
            int r = i >> 7, c = i & 127;
            g_W0p[i] = (r < 127) ? W0[r * 128 + c] : 0.f;
        } else if (i < T0 + T1) {
            int j = i - T0; int r = j >> 7, c = j & 127;
            g_W2xp[j] = (r < 127) ? W2[r * 128 + c] : 0.f;
        } else if (i < T0 + T1 + T2) {
            int j = i - T0 - T1; int r = j >> 7, c = j & 127;
            g_W2hp[j] = W2[(127 + r) * 128 + c];
        } else {
            int j = i - T0 - T1 - T2;
            g_Wdfp[j] = Wd[j];
        }
    }
}

// --------------------- pack xyz / dir embeddings ---------------------------
__global__ void pack_inputs(const float* __restrict__ xyzdir) {
    const int TA = NQ * 64;
    const int total = NQ * 64 + NQ * 32;
    for (int i = blockIdx.x * blockDim.x + threadIdx.x; i < total;
         i += gridDim.x * blockDim.x) {
        if (i < TA) {
            int q = i >> 6, e = i & 63;
            g_X[q * 128 + 64 + e] = (e < 63) ? xyzdir[q * 90 + e] : 0.f;
        } else {
            int j = i - TA; int q = j >> 5, e = j & 31;
            g_DIR[j] = (e < 27) ? xyzdir[q * 90 + 63 + e] : 0.f;
        }
    }
}

// ---------------- V = dir @ Wd[128:155] + bd  ------------------------------
__global__ void __launch_bounds__(256) vcomp(const float* __restrict__ Wd,
                                             const float* __restrict__ bd) {
    __shared__ float sw[27 * 64];
    __shared__ float sb[64];
    int tid = threadIdx.x;
    for (int i = tid; i < 27 * 64; i += 256) sw[i] = Wd[128 * 64 + i];
    if (tid < 64) sb[tid] = bd[tid];
    __syncthreads();
    int idx = blockIdx.x * 256 + tid;
    int q = idx >> 4, c0 = (idx & 15) * 4;
    float a0 = sb[c0], a1 = sb[c0 + 1], a2 = sb[c0 + 2], a3 = sb[c0 + 3];
#pragma unroll
    for (int k = 0; k < 27; k++) {
        float dv = g_DIR[q * 32 + k];
        a0 = fmaf(dv, sw[k * 64 + c0 + 0], a0);
        a1 = fmaf(dv, sw[k * 64 + c0 + 1], a1);
        a2 = fmaf(dv, sw[k * 64 + c0 + 2], a2);
        a3 = fmaf(dv, sw[k * 64 + c0 + 3], a3);
    }
    *reinterpret_cast<float4*>(g_V + (size_t)q * 64 + c0) = make_float4(a0, a1, a2, a3);
}

// --------- KNN(16) + interpolation, fused; clustered queries ---------------
__global__ void __launch_bounds__(128) knn_interp(const int* __restrict__ indices,
                                                  const float* __restrict__ qp,
                                                  const float* __restrict__ cpos,
                                                  const float* __restrict__ codes) {
    __shared__ float4 sp[NC];      // {x, y, z, ||c||^2}
    __shared__ float s_w[128 * 16];
    __shared__ int   s_i[128 * 16];
    int tid = threadIdx.x;
    int ib = indices[0];
    const float* cp = cpos + (size_t)ib * NC * 3;
    const float* cc = codes + (size_t)ib * NC * 64;
    for (int c = tid; c < NC; c += 128) {
        float x = cp[c * 3 + 0], y = cp[c * 3 + 1], z = cp[c * 3 + 2];
        sp[c] = make_float4(x, y, z, fmaf(x, x, fmaf(y, y, z * z)));
    }
    __syncthreads();

    int q = g_perm[blockIdx.x * 128 + tid];
    float qx = qp[q * 3 + 0], qy = qp[q * 3 + 1], qz = qp[q * 3 + 2];
    float qx2 = -2.f * qx, qy2 = -2.f * qy, qz2 = -2.f * qz;
    float q2 = fmaf(qx, qx, fmaf(qy, qy, qz * qz));

    unsigned bk[16];
#pragma unroll
    for (int j = 0; j < 16; j++) bk[j] = 0x7F7FFFFFu;
    float bnd = __uint_as_float(0x7F7FF800u) - q2;   // d2' threshold

    for (int c = 0; c < NC; c += 4) {
#pragma unroll
        for (int i = 0; i < 4; i++) {
            float4 v = sp[c + i];
            float dp = fmaf(v.x, qx2, fmaf(v.y, qy2, fmaf(v.z, qz2, v.w)));
            if (dp < bnd) {
                float dfull = fmaxf(dp + q2, 0.f);   // clamp: keep bits ordered
                unsigned cur = (__float_as_uint(dfull) & 0xFFFFF800u)
                             | (unsigned)(c + i);
#pragma unroll
                for (int j = 0; j < 16; j++) {
                    unsigned mn = min(bk[j], cur);
                    unsigned mx = max(bk[j], cur);
                    bk[j] = mn; cur = mx;
                }
                bnd = __uint_as_float(bk[15] & 0xFFFFF800u) - q2;
            }
        }
    }

    // exact distances -> normalized 1/d2 weights
    float w[16]; int ci[16]; float wsum = 0.f;
#pragma unroll
    for (int k = 0; k < 16; k++) {
        int c = (int)(bk[k] & 0x7FFu); ci[k] = c;
        float4 v = sp[c];
        float dx = qx - v.x, dy = qy - v.y, dz = qz - v.z;
        float d2 = fmaf(dx, dx, fmaf(dy, dy, dz * dz)) + 1e-16f;
        w[k] = 1.0f / d2; wsum += w[k];
    }
    float inv = 1.0f / wsum;
#pragma unroll
    for (int k = 0; k < 16; k++) {
        s_w[tid * 16 + k] = w[k] * inv;
        s_i[tid * 16 + k] = ci[k];
    }
    __syncwarp();

    // warp-cooperative gather: lanes cover 64 code dims, coalesced rows
    int lane = tid & 31;
    int wbase2 = tid & ~31;
    // per-slot query ids for this warp (to address g_X by original q)
    for (int s = 0; s < 32; s++) {
        int t = wbase2 + s;
        int qq = __shfl_sync(0xFFFFFFFFu, q, s);
        float a0 = 0.f, a1 = 0.f;
#pragma unroll
        for (int k = 0; k < 16; k++) {
            int cix = s_i[t * 16 + k];
            float wk = s_w[t * 16 + k];
            const float* row = cc + cix * 64;
            a0 = fmaf(wk, row[lane], a0);
            a1 = fmaf(wk, row[lane + 32], a1);
        }
        g_X[(size_t)qq * 128 + lane] = a0;
        g_X[(size_t)qq * 128 + 32 + lane] = a1;
    }
}

// ===================== fused MLP (entire network) ==========================
#define SMEM_FLOATS (128 * AS + 2 * 32 * WS + 128 + 192)

__global__ void __launch_bounds__(256, 2) fused_mlp(
    const float* __restrict__ W1, const float* __restrict__ W3,
    const float* __restrict__ Wf,
    const float* __restrict__ b0, const float* __restrict__ b1,
    const float* __restrict__ b2, const float* __restrict__ b3,
    const float* __restrict__ bf,
    const float* __restrict__ Wsig, const float* __restrict__ bs,
    const float* __restrict__ Wr,   const float* __restrict__ br,
    float* __restrict__ out)
{
    extern __shared__ float sm[];
    float* A   = sm;
    float* Wb  = sm + 128 * AS;
    float* wsv = Wb + 2 * 32 * WS;
    float* wrv = wsv + 128;

    int tid = threadIdx.x;
    int tx = tid & 15, ty = tid >> 4;
    int rowBlk = blockIdx.x * 128;
    const int wbase = tx * 8 + (tx >> 2) * 4;

    if (tid < 128) wsv[tid] = Wsig[tid];
    if (tid < 192) wrv[tid] = Wr[tid];

    {
        const float4* src = reinterpret_cast<const float4*>(g_X + (size_t)rowBlk * 128);
#pragma unroll
        for (int i = 0; i < 16; i++) {
            int f4 = tid + i * 256;
            float4 v = src[f4];
            int row = f4 >> 5, c4 = f4 & 31;
            *reinterpret_cast<float4*>(A + row * AS + c4 * 4) = v;
        }
    }

    const float* Wgs[6] = { g_W2xp, g_W0p, W1, g_W2hp, W3, Wf };
    const float* bgs[6] = { b0, b0, b1, b2, b3, bf };

    float sigR = 0.f;
    ull acc[8][4];

    for (int L = 0; L < 6; ++L) {
        const float* Wg = Wgs[L];
#pragma unroll
        for (int i = 0; i < 8; i++)
#pragma unroll
            for (int j = 0; j < 4; j++) acc[i][j] = 0ULL;

#pragma unroll
        for (int i = 0; i < 4; i++) {
            float4 v = reinterpret_cast<const float4*>(Wg)[tid * 4 + i];
            int flat = tid * 16 + i * 4;
            int k = flat >> 7, col = flat & 127;
            *reinterpret_cast<float4*>(Wb + k * WS + wsw(col)) = v;
        }
        __syncthreads();

        for (int t = 0; t < 4; t++) {
            float4 pf[4];
            if (t < 3) {
                const float4* g = reinterpret_cast<const float4*>(Wg + (t + 1) * 4096);
#pragma unroll
                for (int i = 0; i < 4; i++) pf[i] = g[tid * 4 + i];
            }
            const float* Wt = Wb + (t & 1) * (32 * WS);
#pragma unroll
            for (int k4 = 0; k4 < 8; k4++) {
                // weights loaded directly as packed f32x2 pairs (no MOV repack)
                ulonglong2 wq0[4], wq1[4];
#pragma unroll
                for (int kk = 0; kk < 4; kk++) {
                    const float* wp = Wt + (k4 * 4 + kk) * WS + wbase;
                    wq0[kk] = *reinterpret_cast<const ulonglong2*>(wp);
                    wq1[kk] = *reinterpret_cast<const ulonglong2*>(wp + 4);
                }
#pragma unroll
                for (int r4 = 0; r4 < 2; r4++) {
                    float4 ar[4];
#pragma unroll
                    for (int r = 0; r < 4; r++)
                        ar[r] = *reinterpret_cast<const float4*>(
                            A + (ty * 8 + r4 * 4 + r) * AS + t * 32 + k4 * 4);
#pragma unroll
                    for (int kk = 0; kk < 4; kk++) {
#pragma unroll
                        for (int r = 0; r < 4; r++) {
                            float av = (kk == 0) ? ar[r].x : (kk == 1) ? ar[r].y
                                     : (kk == 2) ? ar[r].z : ar[r].w;
                            ull ad = pk2(av, av);
                            int ri = r4 * 4 + r;
                            fma2(acc[ri][0], ad, wq0[kk].x);
                            fma2(acc[ri][1], ad, wq0[kk].y);
                            fma2(acc[ri][2], ad, wq1[kk].x);
                            fma2(acc[ri][3], ad, wq1[kk].y);
                        }
                    }
                }
            }
            if (t < 3) {
                float* d = Wb + ((t + 1) & 1) * (32 * WS);
#pragma unroll
                for (int i = 0; i < 4; i++) {
                    int flat = tid * 16 + i * 4;
                    int k = flat >> 7, col = flat & 127;
                    *reinterpret_cast<float4*>(d + k * WS + wsw(col)) = pf[i];
                }
            }
            __syncthreads();
        }

        if (L == 0) {
#pragma unroll
            for (int i = 0; i < 8; i++) {
                size_t row = (size_t)(rowBlk + ty * 8 + i);
                float o[8];
#pragma unroll
                for (int j = 0; j < 4; j++) {
                    float2 v = up2(acc[i][j]); o[2 * j] = v.x; o[2 * j + 1] = v.y;
                }
                *reinterpret_cast<float4*>(g_U + row * 128 + tx * 8) =
                    make_float4(o[0], o[1], o[2], o[3]);
                *reinterpret_cast<float4*>(g_U + row * 128 + tx * 8 + 4) =
                    make_float4(o[4], o[5], o[6], o[7]);
            }
        } else {
            const float* bg = bgs[L];
            float4 bA = *reinterpret_cast<const float4*>(bg + tx * 8);
            float4 bB = *reinterpret_cast<const float4*>(bg + tx * 8 + 4);
            bool relu = (L != 5);
#pragma unroll
            for (int i = 0; i < 8; i++) {
                int row = ty * 8 + i;
                float o[8];
#pragma unroll
                for (int j = 0; j < 4; j++) {
                    float2 v = up2(acc[i][j]); o[2 * j] = v.x; o[2 * j + 1] = v.y;
                }
                if (L == 3) {
                    size_t gr = (size_t)(rowBlk + row);
                    float4 u0 = *reinterpret_cast<const float4*>(g_U + gr * 128 + tx * 8);
                    float4 u1 = *reinterpret_cast<const float4*>(g_U + gr * 128 + tx * 8 + 4);
                    o[0] += u0.x; o[1] += u0.y; o[2] += u0.z; o[3] += u0.w;
                    o[4] += u1.x; o[5] += u1.y; o[6] += u1.z; o[7] += u1.w;
                }
                o[0] += bA.x; o[1] += bA.y; o[2] += bA.z; o[3] += bA.w;
                o[4] += bB.x; o[5] += bB.y; o[6] += bB.z; o[7] += bB.w;
                if (relu) {
#pragma unroll
                    for (int c = 0; c < 8; c++) o[c] = fmaxf(o[c], 0.f);
                }
                *reinterpret_cast<float4*>(A + row * AS + tx * 8) =
                    make_float4(o[0], o[1], o[2], o[3]);
                *reinterpret_cast<float4*>(A + row * AS + tx * 8 + 4) =
                    make_float4(o[4], o[5], o[6], o[7]);
            }
        }
        __syncthreads();

        if (L == 4 && tid < 128) {
            float s = 0.f;
#pragma unroll
            for (int k4 = 0; k4 < 32; k4++) {
                float4 hv = *reinterpret_cast<const float4*>(A + tid * AS + k4 * 4);
                s = fmaf(hv.x, wsv[k4 * 4 + 0], s);
                s = fmaf(hv.y, wsv[k4 * 4 + 1], s);
                s = fmaf(hv.z, wsv[k4 * 4 + 2], s);
                s = fmaf(hv.w, wsv[k4 * 4 + 3], s);
            }
            sigR = s + bs[0];
        }
    }

    // ---- dir layer ----
    int tx8 = tid & 7, ty32 = tid >> 3;
    const int wb64 = tx8 * 8 + (tx8 >> 2) * 4;
    ull acc2[4][4];
#pragma unroll
    for (int i = 0; i < 4; i++)
#pragma unroll
        for (int j = 0; j < 4; j++) acc2[i][j] = 0ULL;

#pragma unroll
    for (int i = 0; i < 2; i++) {
        float4 v = reinterpret_cast<const float4*>(g_Wdfp)[tid * 2 + i];
        int flat = tid * 8 + i * 4;
        int k = flat >> 6, col = flat & 63;
        *reinterpret_cast<float4*>(Wb + k * WS + wsw(col)) = v;
    }
    __syncthreads();

    for (int t = 0; t < 4; t++) {
        float4 pf[2];
        if (t < 3) {
            const float4* g = reinterpret_cast<const float4*>(g_Wdfp + (t + 1) * 2048);
#pragma unroll
            for (int i = 0; i < 2; i++) pf[i] = g[tid * 2 + i];
        }
        const float* Wt = Wb + (t & 1) * (32 * WS);
#pragma unroll
        for (int k4 = 0; k4 < 8; k4++) {
            ulonglong2 wq0[4], wq1[4];
#pragma unroll
            for (int kk = 0; kk < 4; kk++) {
                const float* wp = Wt + (k4 * 4 + kk) * WS + wb64;
                wq0[kk] = *reinterpret_cast<const ulonglong2*>(wp);
                wq1[kk] = *reinterpret_cast<const ulonglong2*>(wp + 4);
            }
            float4 ar[4];
#pragma unroll
            for (int r = 0; r < 4; r++)
                ar[r] = *reinterpret_cast<const float4*>(
                    A + (ty32 * 4 + r) * AS + t * 32 + k4 * 4);
#pragma unroll
            for (int kk = 0; kk < 4; kk++) {
#pragma unroll
                for (int r = 0; r < 4; r++) {
                    float av = (kk == 0) ? ar[r].x : (kk == 1) ? ar[r].y
                             : (kk == 2) ? ar[r].z : ar[r].w;
                    ull ad = pk2(av, av);
                    fma2(acc2[r][0], ad, wq0[kk].x);
                    fma2(acc2[r][1], ad, wq0[kk].y);
                    fma2(acc2[r][2], ad, wq1[kk].x);
                    fma2(acc2[r][3], ad, wq1[kk].y);
                }
            }
        }
        if (t < 3) {
            float* d = Wb + ((t + 1) & 1) * (32 * WS);
#pragma unroll
            for (int i = 0; i < 2; i++) {
                int flat = tid * 8 + i * 4;
                int k = flat >> 6, col = flat & 63;
                *reinterpret_cast<float4*>(d + k * WS + wsw(col)) = pf[i];
            }
        }
        __syncthreads();
    }

#pragma unroll
    for (int r = 0; r < 4; r++) {
        int row = ty32 * 4 + r;
        size_t gr = (size_t)(rowBlk + row);
        float4 v0 = *reinterpret_cast<const float4*>(g_V + gr * 64 + tx8 * 8);
        float4 v1 = *reinterpret_cast<const float4*>(g_V + gr * 64 + tx8 * 8 + 4);
        float o[8];
#pragma unroll
        for (int j = 0; j < 4; j++) {
            float2 v = up2(acc2[r][j]); o[2 * j] = v.x; o[2 * j + 1] = v.y;
        }
        o[0] += v0.x; o[1] += v0.y; o[2] += v0.z; o[3] += v0.w;
        o[4] += v1.x; o[5] += v1.y; o[6] += v1.z; o[7] += v1.w;
#pragma unroll
        for (int c = 0; c < 8; c++) o[c] = fmaxf(o[c], 0.f);
        *reinterpret_cast<float4*>(A + row * AS + tx8 * 8) =
            make_float4(o[0], o[1], o[2], o[3]);
        *reinterpret_cast<float4*>(A + row * AS + tx8 * 8 + 4) =
            make_float4(o[4], o[5], o[6], o[7]);
    }
    __syncthreads();

    if (tid < 128) {
        float r0 = br[0], r1 = br[1], r2 = br[2];
#pragma unroll
        for (int k4 = 0; k4 < 16; k4++) {
            float4 dv = *reinterpret_cast<const float4*>(A + tid * AS + k4 * 4);
            const float* wr0 = wrv + k4 * 12;
            r0 = fmaf(dv.x, wr0[0], r0); r1 = fmaf(dv.x, wr0[1], r1); r2 = fmaf(dv.x, wr0[2], r2);
            r0 = fmaf(dv.y, wr0[3], r0); r1 = fmaf(dv.y, wr0[4], r1); r2 = fmaf(dv.y, wr0[5], r2);
            r0 = fmaf(dv.z, wr0[6], r0); r1 = fmaf(dv.z, wr0[7], r1); r2 = fmaf(dv.z, wr0[8], r2);
            r0 = fmaf(dv.w, wr0[9], r0); r1 = fmaf(dv.w, wr0[10], r1); r2 = fmaf(dv.w, wr0[11], r2);
        }
        *reinterpret_cast<float4*>(out + (size_t)(rowBlk + tid) * 4) =
            make_float4(r0, r1, r2, sigR);
    }
}

// ---------------------------------------------------------------------------
extern "C" void kernel_launch(void* const* d_in, const int* in_sizes, int n_in,
                              void* d_out, int out_size) {
    const int*   indices = (const int*)  d_in[0];
    const float* qp      = (const float*)d_in[1];
    const float* xyzdir  = (const float*)d_in[2];
    const float* cpos    = (const float*)d_in[3];
    const float* codes   = (const float*)d_in[4];
    const float* W0 = (const float*)d_in[5],  *b0 = (const float*)d_in[6];
    const float* W1 = (const float*)d_in[7],  *b1 = (const float*)d_in[8];
    const float* W2 = (const float*)d_in[9],  *b2 = (const float*)d_in[10];
    const float* W3 = (const float*)d_in[11], *b3 = (const float*)d_in[12];
    const float* Wf = (const float*)d_in[13], *bf = (const float*)d_in[14];
    const float* Wd = (const float*)d_in[15], *bd = (const float*)d_in[16];
    const float* Ws = (const float*)d_in[17], *bs = (const float*)d_in[18];
    const float* Wr = (const float*)d_in[19], *br = (const float*)d_in[20];
    float* out = (float*)d_out;

    const int smemBytes = SMEM_FLOATS * 4;
    cudaFuncSetAttribute(fused_mlp, cudaFuncAttributeMaxDynamicSharedMemorySize,
                         smemBytes);

    zero_hist<<<16, 256>>>();
    hist_k<<<NQ / 256, 256>>>(qp);
    scan_k<<<1, 1024>>>();
    scatter_k<<<NQ / 256, 256>>>(qp);
    prep_weights<<<224, 256>>>(W0, W2, Wd);
    pack_inputs<<<1024, 256>>>(xyzdir);
    vcomp<<<NQ * 16 / 256, 256>>>(Wd, bd);
    knn_interp<<<NQ / 128, 128>>>(indices, qp, cpos, codes);
    fused_mlp<<<NQ / 128, 256, smemBytes>>>(W1, W3, Wf, b0, b1, b2, b3, bf,
                                            Ws, bs, Wr, br, out);
}